// round 1
// baseline (speedup 1.0000x reference)
#include <cuda_runtime.h>
#include <math.h>

#define BZ    4
#define SEQ   256
#define DM    1024
#define HID   4096
#define VOCAB 32000
#define NH    16
#define DH    64
#define NL    6
#define ROWS  (BZ*SEQ)   // 1024

// ---------------- scratch (no allocations allowed) ----------------
__device__ float g_h   [ROWS*DM];
__device__ float g_q   [ROWS*DM];
__device__ float g_k   [ROWS*DM];
__device__ float g_v   [ROWS*DM];
__device__ float g_attn[ROWS*DM];
__device__ float g_proj[ROWS*DM];
__device__ float g_y   [ROWS*DM];
__device__ float g_y2  [ROWS*DM];
__device__ float g_ffn [ROWS*HID];
__device__ float g_ffn2[ROWS*DM];
__device__ float g_sc  [BZ*NH*SEQ*SEQ];

// ---------------- embedding + sinusoidal positional encoding ----------------
__global__ void embed_kernel(const int* __restrict__ X,
                             const float* __restrict__ emb,
                             float* __restrict__ h)
{
    int row = blockIdx.x;          // b*SEQ + s
    int s = row % SEQ;
    int tok = X[row];
    const float scale = 32.0f;     // sqrt(1024)
    for (int d = threadIdx.x; d < DM; d += blockDim.x) {
        int j = d & ~1;
        double freq = pow(10000.0, -(double)j / (double)DM);
        double ang  = (double)s * freq;
        float p = (d & 1) ? (float)cos(ang) : (float)sin(ang);
        h[row*DM + d] = emb[tok*DM + d] * scale + p;
    }
}

// ---------------- generic SGEMM: C = A[MxK] @ B[KxN] (+bias)(+relu) ----------------
template<int BM, int BN, int BK, int TM, int TN>
__global__ void __launch_bounds__((BM/TM)*(BN/TN))
sgemm_kernel(const float* __restrict__ A, const float* __restrict__ B,
             const float* __restrict__ bias, float* __restrict__ C,
             int M, int N, int K, int relu)
{
    constexpr int THREADS = (BM/TM)*(BN/TN);
    __shared__ float As[BK][BM];
    __shared__ float Bs[BK][BN];
    const int tid = threadIdx.x;
    const int br = blockIdx.y * BM;
    const int bc = blockIdx.x * BN;
    const int tr = tid / (BN/TN);
    const int tc = tid % (BN/TN);

    float acc[TM][TN];
    #pragma unroll
    for (int i = 0; i < TM; i++)
        #pragma unroll
        for (int j = 0; j < TN; j++) acc[i][j] = 0.f;

    for (int k0 = 0; k0 < K; k0 += BK) {
        #pragma unroll 2
        for (int i = tid; i < BM*BK; i += THREADS) {
            int m  = i / BK;
            int kk = i % BK;
            As[kk][m] = A[(br+m)*K + k0 + kk];
        }
        #pragma unroll 2
        for (int i = tid; i < BK*BN; i += THREADS) {
            int kk = i / BN;
            int n  = i % BN;
            Bs[kk][n] = B[(size_t)(k0+kk)*N + bc + n];
        }
        __syncthreads();
        #pragma unroll
        for (int kk = 0; kk < BK; kk++) {
            float a[TM], b[TN];
            #pragma unroll
            for (int i = 0; i < TM; i++) a[i] = As[kk][tr*TM + i];
            #pragma unroll
            for (int j = 0; j < TN; j++) b[j] = Bs[kk][tc*TN + j];
            #pragma unroll
            for (int i = 0; i < TM; i++)
                #pragma unroll
                for (int j = 0; j < TN; j++) acc[i][j] += a[i]*b[j];
        }
        __syncthreads();
    }
    #pragma unroll
    for (int i = 0; i < TM; i++) {
        int r = br + tr*TM + i;
        #pragma unroll
        for (int j = 0; j < TN; j++) {
            int c = bc + tc*TN + j;
            float v = acc[i][j];
            if (bias) v += bias[c];
            if (relu) v = fmaxf(v, 0.f);
            C[(size_t)r*N + c] = v;
        }
    }
}

// ---------------- attention scores: S = QK^T/8 with reference mask (fill 1e-6) ----------------
// mode 0: self-attn, per-query valid = min(dec_valid[b], i+1)
// mode 1: cross-attn, valid = enc_valid[b]
__global__ void scores_kernel(const float* __restrict__ Q, const float* __restrict__ Kv,
                              float* __restrict__ Sc, const int* __restrict__ valid,
                              int mode)
{
    int bh = blockIdx.z, b = bh / NH, h = bh % NH;
    int i0 = blockIdx.y * 16, j0 = blockIdx.x * 16;
    __shared__ float Qs[16][DH];
    __shared__ float Ks[16][DH+1];
    int tid = threadIdx.y*16 + threadIdx.x;
    for (int idx = tid; idx < 16*DH; idx += 256) {
        int r = idx / DH, d = idx % DH;
        Qs[r][d] = Q [(b*SEQ + i0 + r)*DM + h*DH + d];
        Ks[r][d] = Kv[(b*SEQ + j0 + r)*DM + h*DH + d];
    }
    __syncthreads();
    int i = i0 + threadIdx.y, j = j0 + threadIdx.x;
    float acc = 0.f;
    #pragma unroll
    for (int d = 0; d < DH; d++) acc += Qs[threadIdx.y][d] * Ks[threadIdx.x][d];
    int vld = (mode == 0) ? min(valid[b], i + 1) : valid[b];
    float val = (j >= vld) ? 1e-6f : acc * 0.125f;
    Sc[(bh*SEQ + i)*SEQ + j] = val;
}

// ---------------- row softmax over 256 keys, one warp per row ----------------
__global__ void softmax_kernel(float* __restrict__ Sc)
{
    int warp = threadIdx.x >> 5, lane = threadIdx.x & 31;
    int row = blockIdx.x * 8 + warp;
    float* p = Sc + (size_t)row * SEQ;
    float vals[8];
    float mx = -1e30f;
    #pragma unroll
    for (int t = 0; t < 8; t++) { vals[t] = p[lane + t*32]; mx = fmaxf(mx, vals[t]); }
    #pragma unroll
    for (int o = 16; o; o >>= 1) mx = fmaxf(mx, __shfl_xor_sync(0xffffffffu, mx, o));
    float sum = 0.f;
    #pragma unroll
    for (int t = 0; t < 8; t++) { vals[t] = expf(vals[t] - mx); sum += vals[t]; }
    #pragma unroll
    for (int o = 16; o; o >>= 1) sum += __shfl_xor_sync(0xffffffffu, sum, o);
    float inv = 1.0f / sum;
    #pragma unroll
    for (int t = 0; t < 8; t++) p[lane + t*32] = vals[t] * inv;
}

// ---------------- O = softmax(S) @ V, written to concatenated [B,S,DM] layout ----------------
__global__ void av_kernel(const float* __restrict__ W, const float* __restrict__ Vv,
                          float* __restrict__ O)
{
    int bh = blockIdx.z, b = bh / NH, h = bh % NH;
    int i0 = blockIdx.y * 16, d0 = blockIdx.x * 16;
    __shared__ float Ws[16][17];
    __shared__ float Vs[16][17];
    float acc = 0.f;
    for (int j0 = 0; j0 < SEQ; j0 += 16) {
        Ws[threadIdx.y][threadIdx.x] = W [(size_t)(bh*SEQ + i0 + threadIdx.y)*SEQ + j0 + threadIdx.x];
        Vs[threadIdx.y][threadIdx.x] = Vv[(b*SEQ + j0 + threadIdx.y)*DM + h*DH + d0 + threadIdx.x];
        __syncthreads();
        #pragma unroll
        for (int jj = 0; jj < 16; jj++) acc += Ws[threadIdx.y][jj] * Vs[jj][threadIdx.x];
        __syncthreads();
    }
    O[(b*SEQ + i0 + threadIdx.y)*DM + h*DH + d0 + threadIdx.x] = acc;
}

// ---------------- out = LayerNorm(a + r) * g + be ----------------
__global__ void add_ln_kernel(const float* __restrict__ a, const float* __restrict__ r,
                              const float* __restrict__ g, const float* __restrict__ be,
                              float* __restrict__ out)
{
    int row = blockIdx.x;
    __shared__ float red[256];
    float x[4];
    #pragma unroll
    for (int t = 0; t < 4; t++) {
        int c = threadIdx.x + t*256;
        x[t] = a[row*DM + c] + r[row*DM + c];
    }
    float s = x[0] + x[1] + x[2] + x[3];
    red[threadIdx.x] = s; __syncthreads();
    for (int o = 128; o; o >>= 1) {
        if (threadIdx.x < o) red[threadIdx.x] += red[threadIdx.x + o];
        __syncthreads();
    }
    float mean = red[0] * (1.0f / DM);
    __syncthreads();
    float vs = 0.f;
    #pragma unroll
    for (int t = 0; t < 4; t++) { float d = x[t] - mean; vs += d*d; }
    red[threadIdx.x] = vs; __syncthreads();
    for (int o = 128; o; o >>= 1) {
        if (threadIdx.x < o) red[threadIdx.x] += red[threadIdx.x + o];
        __syncthreads();
    }
    float inv = rsqrtf(red[0] * (1.0f / DM) + 1e-5f);
    #pragma unroll
    for (int t = 0; t < 4; t++) {
        int c = threadIdx.x + t*256;
        out[row*DM + c] = (x[t] - mean) * inv * g[c] + be[c];
    }
}

// ---------------- host orchestration ----------------
static void gemm64(const float* A, const float* B, const float* bias, float* C,
                   int M, int N, int K, int relu)
{
    dim3 grid(N/64, M/64);
    sgemm_kernel<64,64,16,4,4><<<grid, 256>>>(A, B, bias, C, M, N, K, relu);
}
static void gemm128(const float* A, const float* B, const float* bias, float* C,
                    int M, int N, int K, int relu)
{
    dim3 grid(N/128, M/128);
    sgemm_kernel<128,128,8,8,8><<<grid, 256>>>(A, B, bias, C, M, N, K, relu);
}

extern "C" void kernel_launch(void* const* d_in, const int* in_sizes, int n_in,
                              void* d_out, int out_size)
{
    const int*   X         = (const int*)  d_in[0];
    const int*   dec_valid = (const int*)  d_in[1];
    const float* enc_out   = (const float*)d_in[2];
    const int*   enc_valid = (const int*)  d_in[3];
    const float* emb       = (const float*)d_in[4];
    const float* Wq1 = (const float*)d_in[5];
    const float* Wk1 = (const float*)d_in[6];
    const float* Wv1 = (const float*)d_in[7];
    const float* Wo1 = (const float*)d_in[8];
    const float* Wq2 = (const float*)d_in[9];
    const float* Wk2 = (const float*)d_in[10];
    const float* Wv2 = (const float*)d_in[11];
    const float* Wo2 = (const float*)d_in[12];
    const float* W1  = (const float*)d_in[13];
    const float* W2  = (const float*)d_in[14];
    const float* Wout= (const float*)d_in[15];
    const float* b1  = (const float*)d_in[16];
    const float* b2  = (const float*)d_in[17];
    const float* bout= (const float*)d_in[18];
    const float* ln1g= (const float*)d_in[19];
    const float* ln1b= (const float*)d_in[20];
    const float* ln2g= (const float*)d_in[21];
    const float* ln2b= (const float*)d_in[22];
    const float* ln3g= (const float*)d_in[23];
    const float* ln3b= (const float*)d_in[24];
    float* out = (float*)d_out;

    float *h, *q, *k, *v, *attn, *proj, *y, *y2, *ffn, *ffn2, *sc;
    cudaGetSymbolAddress((void**)&h,    g_h);
    cudaGetSymbolAddress((void**)&q,    g_q);
    cudaGetSymbolAddress((void**)&k,    g_k);
    cudaGetSymbolAddress((void**)&v,    g_v);
    cudaGetSymbolAddress((void**)&attn, g_attn);
    cudaGetSymbolAddress((void**)&proj, g_proj);
    cudaGetSymbolAddress((void**)&y,    g_y);
    cudaGetSymbolAddress((void**)&y2,   g_y2);
    cudaGetSymbolAddress((void**)&ffn,  g_ffn);
    cudaGetSymbolAddress((void**)&ffn2, g_ffn2);
    cudaGetSymbolAddress((void**)&sc,   g_sc);

    embed_kernel<<<ROWS, 256>>>(X, emb, h);

    dim3 sgrid(SEQ/16, SEQ/16, BZ*NH);
    dim3 agrid(DH/16,  SEQ/16, BZ*NH);
    dim3 tb16(16, 16);
    int  smrows = BZ*NH*SEQ/8;

    for (int l = 0; l < NL; l++) {
        const size_t o2 = (size_t)l*DM*DM;
        // ---- self attention ----
        gemm64(h, Wq1+o2, nullptr, q, ROWS, DM, DM, 0);
        gemm64(h, Wk1+o2, nullptr, k, ROWS, DM, DM, 0);
        gemm64(h, Wv1+o2, nullptr, v, ROWS, DM, DM, 0);
        scores_kernel<<<sgrid, tb16>>>(q, k, sc, dec_valid, 0);
        softmax_kernel<<<smrows, 256>>>(sc);
        av_kernel<<<agrid, tb16>>>(sc, v, attn);
        gemm64(attn, Wo1+o2, nullptr, proj, ROWS, DM, DM, 0);
        add_ln_kernel<<<ROWS, 256>>>(h, proj, ln1g + l*DM, ln1b + l*DM, y);
        // ---- cross attention ----
        gemm64(y,       Wq2+o2, nullptr, q, ROWS, DM, DM, 0);
        gemm64(enc_out, Wk2+o2, nullptr, k, ROWS, DM, DM, 0);
        gemm64(enc_out, Wv2+o2, nullptr, v, ROWS, DM, DM, 0);
        scores_kernel<<<sgrid, tb16>>>(q, k, sc, enc_valid, 1);
        softmax_kernel<<<smrows, 256>>>(sc);
        av_kernel<<<agrid, tb16>>>(sc, v, attn);
        gemm64(attn, Wo2+o2, nullptr, proj, ROWS, DM, DM, 0);
        add_ln_kernel<<<ROWS, 256>>>(y, proj, ln2g + l*DM, ln2b + l*DM, y2);
        // ---- FFN ----
        gemm128(y2,  W1 + (size_t)l*DM*HID, b1 + l*HID, ffn,  ROWS, HID, DM, 1);
        gemm64 (ffn, W2 + (size_t)l*HID*DM, b2 + l*DM,  ffn2, ROWS, DM, HID, 0);
        add_ln_kernel<<<ROWS, 256>>>(y2, ffn2, ln3g + l*DM, ln3b + l*DM, h);
    }
    // ---- final vocab projection ----
    gemm128(h, Wout, bout, out, ROWS, VOCAB, DM, 0);
}

// round 2
// speedup vs baseline: 1.2138x; 1.2138x over previous
#include <cuda_runtime.h>
#include <math.h>
#include <stdint.h>

#define BZ    4
#define SEQ   256
#define DM    1024
#define HID   4096
#define VOCAB 32000
#define NH    16
#define DH    64
#define NL    6
#define ROWS  (BZ*SEQ)   // 1024

// ---------------- scratch (no allocations allowed) ----------------
__device__ float g_h   [ROWS*DM];
__device__ float g_q   [ROWS*DM];
__device__ float g_k   [ROWS*DM];
__device__ float g_v   [ROWS*DM];
__device__ float g_attn[ROWS*DM];
__device__ float g_proj[ROWS*DM];
__device__ float g_y   [ROWS*DM];
__device__ float g_y2  [ROWS*DM];
__device__ float g_ffn [ROWS*HID];
__device__ float g_ffn2[ROWS*DM];
__device__ float g_sc  [BZ*NH*SEQ*SEQ];

// ---------------- helpers ----------------
__device__ __forceinline__ uint32_t f2tf32(float f) {
    uint32_t r;
    asm("cvt.rna.tf32.f32 %0, %1;" : "=r"(r) : "f"(f));
    return r;
}

__device__ __forceinline__ void mma_tf32(float c[4],
    uint32_t a0, uint32_t a1, uint32_t a2, uint32_t a3,
    uint32_t b0, uint32_t b1)
{
    asm("mma.sync.aligned.m16n8k8.row.col.f32.tf32.tf32.f32 "
        "{%0,%1,%2,%3},{%4,%5,%6,%7},{%8,%9},{%0,%1,%2,%3};"
        : "+f"(c[0]), "+f"(c[1]), "+f"(c[2]), "+f"(c[3])
        : "r"(a0), "r"(a1), "r"(a2), "r"(a3), "r"(b0), "r"(b1));
}

// ---------------- embedding + sinusoidal positional encoding ----------------
__global__ void embed_kernel(const int* __restrict__ X,
                             const float* __restrict__ emb,
                             float* __restrict__ h)
{
    int row = blockIdx.x;          // b*SEQ + s
    int s = row % SEQ;
    int tok = X[row];
    const float scale = 32.0f;     // sqrt(1024)
    for (int d = threadIdx.x; d < DM; d += blockDim.x) {
        int j = d & ~1;
        double freq = pow(10000.0, -(double)j / (double)DM);
        double ang  = (double)s * freq;
        float p = (d & 1) ? (float)cos(ang) : (float)sin(ang);
        h[row*DM + d] = emb[tok*DM + d] * scale + p;
    }
}

// ---------------- tf32 tensor-core GEMM ----------------
// C[MxN] = A[MxK] @ B[KxN] (+bias)(+relu)
// Block tile 64x128x32, 8 warps, warp tile 32x32, mma.m16n8k8.tf32.
// SMEM holds fragment-permuted tiles so frag loads are LDS.128 / LDS.64.
__global__ void __launch_bounds__(256, 2)
tgemm_kernel(const float* __restrict__ A, const float* __restrict__ B,
             const float* __restrict__ bias, float* __restrict__ C,
             int M, int N, int K, int relu)
{
    // [kc][tile][lane][reg]
    __shared__ __align__(16) uint32_t sA[4][4][32][4];   // 64x32  (8KB)
    __shared__ __align__(16) uint32_t sB[4][16][32][2];  // 32x128 (16KB)

    const int tid  = threadIdx.x;
    const int br   = blockIdx.y * 64;
    const int bc   = blockIdx.x * 128;
    const int wid  = tid >> 5;
    const int lane = tid & 31;
    const int wm   = wid >> 2;    // 0..1
    const int wn   = wid & 3;     // 0..3

    float acc[2][4][4];
    #pragma unroll
    for (int im = 0; im < 2; im++)
        #pragma unroll
        for (int in = 0; in < 4; in++)
            #pragma unroll
            for (int t = 0; t < 4; t++) acc[im][in][t] = 0.f;

    // global-load geometry
    const int am = tid >> 3;          // 0..31 (plus +32 second half)
    const int ak = (tid & 7) << 2;    // 0,4,...,28
    const int bk = wid;               // 0..7 (plus p*8)
    const int bn = lane << 2;         // 0..124

    const int nkt = K >> 5;

    float4 ra[2], rb[4];

    // prefetch kt = 0
    {
        const float4* pa0 = (const float4*)&A[(size_t)(br + am)      * K + ak];
        const float4* pa1 = (const float4*)&A[(size_t)(br + am + 32) * K + ak];
        ra[0] = *pa0; ra[1] = *pa1;
        #pragma unroll
        for (int p = 0; p < 4; p++)
            rb[p] = *(const float4*)&B[(size_t)(p*8 + bk) * N + bc + bn];
    }

    for (int kt = 0; kt < nkt; kt++) {
        // ---- store staged registers into permuted smem ----
        #pragma unroll
        for (int h = 0; h < 2; h++) {
            int m    = am + h*32;
            int tm   = m >> 4;
            int mm   = m & 15;
            int hi_m = mm >> 3;
            int lb   = (mm & 7) << 2;
            int kc   = ak >> 3;
            int rg   = (((ak >> 2) & 1) << 1) | hi_m;
            const float* f = (const float*)&ra[h];
            #pragma unroll
            for (int j = 0; j < 4; j++)
                sA[kc][tm][lb | j][rg] = f2tf32(f[j]);
        }
        #pragma unroll
        for (int p = 0; p < 4; p++) {
            int rg = bk >> 2;
            int kl = bk & 3;
            const float* f = (const float*)&rb[p];
            #pragma unroll
            for (int j = 0; j < 4; j++) {
                int n = bn + j;
                sB[p][n >> 3][((n & 7) << 2) | kl][rg] = f2tf32(f[j]);
            }
        }
        __syncthreads();

        // ---- prefetch next tile (LDG overlapped with MMA) ----
        if (kt + 1 < nkt) {
            int k0 = (kt + 1) << 5;
            ra[0] = *(const float4*)&A[(size_t)(br + am)      * K + k0 + ak];
            ra[1] = *(const float4*)&A[(size_t)(br + am + 32) * K + k0 + ak];
            #pragma unroll
            for (int p = 0; p < 4; p++)
                rb[p] = *(const float4*)&B[(size_t)(k0 + p*8 + bk) * N + bc + bn];
        }

        // ---- tensor-core compute ----
        #pragma unroll
        for (int kc = 0; kc < 4; kc++) {
            uint4 af[2];
            uint2 bf[4];
            #pragma unroll
            for (int im = 0; im < 2; im++)
                af[im] = *(const uint4*)&sA[kc][wm*2 + im][lane][0];
            #pragma unroll
            for (int in = 0; in < 4; in++)
                bf[in] = *(const uint2*)&sB[kc][wn*4 + in][lane][0];
            #pragma unroll
            for (int im = 0; im < 2; im++)
                #pragma unroll
                for (int in = 0; in < 4; in++)
                    mma_tf32(acc[im][in], af[im].x, af[im].y, af[im].z, af[im].w,
                             bf[in].x, bf[in].y);
        }
        __syncthreads();
    }

    // ---- epilogue ----
    const int r0 = br + wm*32 + (lane >> 2);
    const int c0 = bc + wn*32 + (lane & 3)*2;
    #pragma unroll
    for (int im = 0; im < 2; im++) {
        int r = r0 + im*16;
        #pragma unroll
        for (int in = 0; in < 4; in++) {
            int c = c0 + in*8;
            float2 v0 = make_float2(acc[im][in][0], acc[im][in][1]);
            float2 v1 = make_float2(acc[im][in][2], acc[im][in][3]);
            if (bias) {
                float b0 = bias[c], b1 = bias[c+1];
                v0.x += b0; v0.y += b1; v1.x += b0; v1.y += b1;
            }
            if (relu) {
                v0.x = fmaxf(v0.x, 0.f); v0.y = fmaxf(v0.y, 0.f);
                v1.x = fmaxf(v1.x, 0.f); v1.y = fmaxf(v1.y, 0.f);
            }
            *(float2*)&C[(size_t)r     * N + c] = v0;
            *(float2*)&C[(size_t)(r+8) * N + c] = v1;
        }
    }
}

static void tgemm(const float* A, const float* B, const float* bias, float* C,
                  int M, int N, int K, int relu)
{
    dim3 grid(N/128, M/64);
    tgemm_kernel<<<grid, 256>>>(A, B, bias, C, M, N, K, relu);
}

// ---------------- attention scores: S = QK^T/8 with reference mask (fill 1e-6) ----------------
__global__ void scores_kernel(const float* __restrict__ Q, const float* __restrict__ Kv,
                              float* __restrict__ Sc, const int* __restrict__ valid,
                              int mode)
{
    int bh = blockIdx.z, b = bh / NH, h = bh % NH;
    int i0 = blockIdx.y * 16, j0 = blockIdx.x * 16;
    __shared__ float Qs[16][DH];
    __shared__ float Ks[16][DH+1];
    int tid = threadIdx.y*16 + threadIdx.x;
    for (int idx = tid; idx < 16*DH; idx += 256) {
        int r = idx / DH, d = idx % DH;
        Qs[r][d] = Q [(b*SEQ + i0 + r)*DM + h*DH + d];
        Ks[r][d] = Kv[(b*SEQ + j0 + r)*DM + h*DH + d];
    }
    __syncthreads();
    int i = i0 + threadIdx.y, j = j0 + threadIdx.x;
    float acc = 0.f;
    #pragma unroll
    for (int d = 0; d < DH; d++) acc += Qs[threadIdx.y][d] * Ks[threadIdx.x][d];
    int vld = (mode == 0) ? min(valid[b], i + 1) : valid[b];
    float val = (j >= vld) ? 1e-6f : acc * 0.125f;
    Sc[(bh*SEQ + i)*SEQ + j] = val;
}

// ---------------- row softmax over 256 keys, one warp per row ----------------
__global__ void softmax_kernel(float* __restrict__ Sc)
{
    int warp = threadIdx.x >> 5, lane = threadIdx.x & 31;
    int row = blockIdx.x * 8 + warp;
    float* p = Sc + (size_t)row * SEQ;
    float vals[8];
    float mx = -1e30f;
    #pragma unroll
    for (int t = 0; t < 8; t++) { vals[t] = p[lane + t*32]; mx = fmaxf(mx, vals[t]); }
    #pragma unroll
    for (int o = 16; o; o >>= 1) mx = fmaxf(mx, __shfl_xor_sync(0xffffffffu, mx, o));
    float sum = 0.f;
    #pragma unroll
    for (int t = 0; t < 8; t++) { vals[t] = expf(vals[t] - mx); sum += vals[t]; }
    #pragma unroll
    for (int o = 16; o; o >>= 1) sum += __shfl_xor_sync(0xffffffffu, sum, o);
    float inv = 1.0f / sum;
    #pragma unroll
    for (int t = 0; t < 8; t++) p[lane + t*32] = vals[t] * inv;
}

// ---------------- O = softmax(S) @ V, concat heads into [B,S,DM] ----------------
__global__ void av_kernel(const float* __restrict__ W, const float* __restrict__ Vv,
                          float* __restrict__ O)
{
    int bh = blockIdx.z, b = bh / NH, h = bh % NH;
    int i0 = blockIdx.y * 16, d0 = blockIdx.x * 16;
    __shared__ float Ws[16][17];
    __shared__ float Vs[16][17];
    float acc = 0.f;
    for (int j0 = 0; j0 < SEQ; j0 += 16) {
        Ws[threadIdx.y][threadIdx.x] = W [(size_t)(bh*SEQ + i0 + threadIdx.y)*SEQ + j0 + threadIdx.x];
        Vs[threadIdx.y][threadIdx.x] = Vv[(b*SEQ + j0 + threadIdx.y)*DM + h*DH + d0 + threadIdx.x];
        __syncthreads();
        #pragma unroll
        for (int jj = 0; jj < 16; jj++) acc += Ws[threadIdx.y][jj] * Vs[jj][threadIdx.x];
        __syncthreads();
    }
    O[(b*SEQ + i0 + threadIdx.y)*DM + h*DH + d0 + threadIdx.x] = acc;
}

// ---------------- out = LayerNorm(a + r) * g + be ----------------
__global__ void add_ln_kernel(const float* __restrict__ a, const float* __restrict__ r,
                              const float* __restrict__ g, const float* __restrict__ be,
                              float* __restrict__ out)
{
    int row = blockIdx.x;
    __shared__ float red[256];
    float x[4];
    #pragma unroll
    for (int t = 0; t < 4; t++) {
        int c = threadIdx.x + t*256;
        x[t] = a[row*DM + c] + r[row*DM + c];
    }
    float s = x[0] + x[1] + x[2] + x[3];
    red[threadIdx.x] = s; __syncthreads();
    for (int o = 128; o; o >>= 1) {
        if (threadIdx.x < o) red[threadIdx.x] += red[threadIdx.x + o];
        __syncthreads();
    }
    float mean = red[0] * (1.0f / DM);
    __syncthreads();
    float vs = 0.f;
    #pragma unroll
    for (int t = 0; t < 4; t++) { float d = x[t] - mean; vs += d*d; }
    red[threadIdx.x] = vs; __syncthreads();
    for (int o = 128; o; o >>= 1) {
        if (threadIdx.x < o) red[threadIdx.x] += red[threadIdx.x + o];
        __syncthreads();
    }
    float inv = rsqrtf(red[0] * (1.0f / DM) + 1e-5f);
    #pragma unroll
    for (int t = 0; t < 4; t++) {
        int c = threadIdx.x + t*256;
        out[row*DM + c] = (x[t] - mean) * inv * g[c] + be[c];
    }
}

// ---------------- host orchestration ----------------
extern "C" void kernel_launch(void* const* d_in, const int* in_sizes, int n_in,
                              void* d_out, int out_size)
{
    const int*   X         = (const int*)  d_in[0];
    const int*   dec_valid = (const int*)  d_in[1];
    const float* enc_out   = (const float*)d_in[2];
    const int*   enc_valid = (const int*)  d_in[3];
    const float* emb       = (const float*)d_in[4];
    const float* Wq1 = (const float*)d_in[5];
    const float* Wk1 = (const float*)d_in[6];
    const float* Wv1 = (const float*)d_in[7];
    const float* Wo1 = (const float*)d_in[8];
    const float* Wq2 = (const float*)d_in[9];
    const float* Wk2 = (const float*)d_in[10];
    const float* Wv2 = (const float*)d_in[11];
    const float* Wo2 = (const float*)d_in[12];
    const float* W1  = (const float*)d_in[13];
    const float* W2  = (const float*)d_in[14];
    const float* Wout= (const float*)d_in[15];
    const float* b1  = (const float*)d_in[16];
    const float* b2  = (const float*)d_in[17];
    const float* bout= (const float*)d_in[18];
    const float* ln1g= (const float*)d_in[19];
    const float* ln1b= (const float*)d_in[20];
    const float* ln2g= (const float*)d_in[21];
    const float* ln2b= (const float*)d_in[22];
    const float* ln3g= (const float*)d_in[23];
    const float* ln3b= (const float*)d_in[24];
    float* out = (float*)d_out;

    float *h, *q, *k, *v, *attn, *proj, *y, *y2, *ffn, *ffn2, *sc;
    cudaGetSymbolAddress((void**)&h,    g_h);
    cudaGetSymbolAddress((void**)&q,    g_q);
    cudaGetSymbolAddress((void**)&k,    g_k);
    cudaGetSymbolAddress((void**)&v,    g_v);
    cudaGetSymbolAddress((void**)&attn, g_attn);
    cudaGetSymbolAddress((void**)&proj, g_proj);
    cudaGetSymbolAddress((void**)&y,    g_y);
    cudaGetSymbolAddress((void**)&y2,   g_y2);
    cudaGetSymbolAddress((void**)&ffn,  g_ffn);
    cudaGetSymbolAddress((void**)&ffn2, g_ffn2);
    cudaGetSymbolAddress((void**)&sc,   g_sc);

    embed_kernel<<<ROWS, 256>>>(X, emb, h);

    dim3 sgrid(SEQ/16, SEQ/16, BZ*NH);
    dim3 agrid(DH/16,  SEQ/16, BZ*NH);
    dim3 tb16(16, 16);
    int  smrows = BZ*NH*SEQ/8;

    for (int l = 0; l < NL; l++) {
        const size_t o2 = (size_t)l*DM*DM;
        // ---- self attention ----
        tgemm(h, Wq1+o2, nullptr, q, ROWS, DM, DM, 0);
        tgemm(h, Wk1+o2, nullptr, k, ROWS, DM, DM, 0);
        tgemm(h, Wv1+o2, nullptr, v, ROWS, DM, DM, 0);
        scores_kernel<<<sgrid, tb16>>>(q, k, sc, dec_valid, 0);
        softmax_kernel<<<smrows, 256>>>(sc);
        av_kernel<<<agrid, tb16>>>(sc, v, attn);
        tgemm(attn, Wo1+o2, nullptr, proj, ROWS, DM, DM, 0);
        add_ln_kernel<<<ROWS, 256>>>(h, proj, ln1g + l*DM, ln1b + l*DM, y);
        // ---- cross attention ----
        tgemm(y,       Wq2+o2, nullptr, q, ROWS, DM, DM, 0);
        tgemm(enc_out, Wk2+o2, nullptr, k, ROWS, DM, DM, 0);
        tgemm(enc_out, Wv2+o2, nullptr, v, ROWS, DM, DM, 0);
        scores_kernel<<<sgrid, tb16>>>(q, k, sc, enc_valid, 1);
        softmax_kernel<<<smrows, 256>>>(sc);
        av_kernel<<<agrid, tb16>>>(sc, v, attn);
        tgemm(attn, Wo2+o2, nullptr, proj, ROWS, DM, DM, 0);
        add_ln_kernel<<<ROWS, 256>>>(y, proj, ln2g + l*DM, ln2b + l*DM, y2);
        // ---- FFN ----
        tgemm(y2,  W1 + (size_t)l*DM*HID, b1 + l*HID, ffn,  ROWS, HID, DM, 1);
        tgemm(ffn, W2 + (size_t)l*HID*DM, b2 + l*DM,  ffn2, ROWS, DM, HID, 0);
        add_ln_kernel<<<ROWS, 256>>>(y2, ffn2, ln3g + l*DM, ln3b + l*DM, h);
    }
    // ---- final vocab projection ----
    tgemm(h, Wout, bout, out, ROWS, VOCAB, DM, 0);
}

// round 3
// speedup vs baseline: 3.5364x; 2.9135x over previous
#include <cuda_runtime.h>
#include <math.h>
#include <stdint.h>

#define BZ    4
#define SEQ   256
#define DM    1024
#define HID   4096
#define VOCAB 32000
#define NH    16
#define DH    64
#define NL    6
#define ROWS  (BZ*SEQ)   // 1024

// ---------------- scratch (no allocations allowed) ----------------
__device__ float g_h   [ROWS*DM];
__device__ float g_q   [ROWS*DM];
__device__ float g_k   [ROWS*DM];
__device__ float g_v   [ROWS*DM];
__device__ float g_attn[ROWS*DM];
__device__ float g_proj[ROWS*DM];
__device__ float g_y   [ROWS*DM];
__device__ float g_y2  [ROWS*DM];
__device__ float g_ffn [ROWS*HID];
__device__ float g_ffn2[ROWS*DM];
__device__ float g_sc  [BZ*NH*SEQ*SEQ];

struct Ptrs3 {
    const float* B[3];
    float*       C[3];
};

// ---------------- helpers ----------------
__device__ __forceinline__ uint32_t f2tf32(float f) {
    uint32_t r;
    asm("cvt.rna.tf32.f32 %0, %1;" : "=r"(r) : "f"(f));
    return r;
}

__device__ __forceinline__ void mma_tf32(float c[4],
    uint32_t a0, uint32_t a1, uint32_t a2, uint32_t a3,
    uint32_t b0, uint32_t b1)
{
    asm("mma.sync.aligned.m16n8k8.row.col.f32.tf32.tf32.f32 "
        "{%0,%1,%2,%3},{%4,%5,%6,%7},{%8,%9},{%0,%1,%2,%3};"
        : "+f"(c[0]), "+f"(c[1]), "+f"(c[2]), "+f"(c[3])
        : "r"(a0), "r"(a1), "r"(a2), "r"(a3), "r"(b0), "r"(b1));
}

// ---------------- embedding + sinusoidal positional encoding ----------------
__global__ void embed_kernel(const int* __restrict__ X,
                             const float* __restrict__ emb,
                             float* __restrict__ h)
{
    int row = blockIdx.x;          // b*SEQ + s
    int s = row % SEQ;
    int tok = X[row];
    const float scale = 32.0f;     // sqrt(1024)
    const float l2 = 13.28771238f; // log2(10000)
    for (int d = threadIdx.x; d < DM; d += blockDim.x) {
        int j = d & ~1;
        float freq = exp2f(-((float)j / (float)DM) * l2);
        float ang  = (float)s * freq;
        float sn, cs;
        sincosf(ang, &sn, &cs);
        float p = (d & 1) ? cs : sn;
        h[row*DM + d] = emb[tok*DM + d] * scale + p;
    }
}

// ---------------- tf32 tensor-core GEMM ----------------
// Block tile (WM*32)x(WN*32)x32, warp tile 32x32, mma m16n8k8 tf32.
// Double-buffered SMEM, XOR-swizzled row-major tiles, STS.128 stores,
// conflict-free LDS.32 fragment loads. grid.z batches over B/C pointers.
template<int WM, int WN>
__global__ void __launch_bounds__(WM*WN*32, (WM*WN == 4) ? 4 : 2)
tgemm_kernel(const float* __restrict__ A, Ptrs3 P,
             const float* __restrict__ bias, int M, int N, int K, int relu)
{
    constexpr int BM  = WM*32;
    constexpr int BN  = WN*32;
    constexpr int T   = WM*WN*32;
    constexpr int ITA = BM*8 / T;      // A: BM rows x 8 chunks of 16B
    constexpr int BC  = BN/4;          // B chunks per row
    constexpr int ITB = 32*BC / T;

    __shared__ __align__(16) uint32_t sA[2][BM*32];
    __shared__ __align__(16) uint32_t sB[2][32*BN];

    const float* __restrict__ Bp = P.B[blockIdx.z];
    float*       __restrict__ Cp = P.C[blockIdx.z];

    const int tid  = threadIdx.x;
    const int br   = blockIdx.y * BM;
    const int bc   = blockIdx.x * BN;
    const int wid  = tid >> 5;
    const int lane = tid & 31;
    const int wm   = wid / WN;
    const int wn   = wid % WN;
    const int rl   = lane >> 2;   // 0..7
    const int w    = lane & 3;    // 0..3

    float acc[2][4][4];
    #pragma unroll
    for (int im = 0; im < 2; im++)
        #pragma unroll
        for (int in = 0; in < 4; in++)
            #pragma unroll
            for (int t = 0; t < 4; t++) acc[im][in][t] = 0.f;

    float4 ra[ITA], rb[ITB];

    const int nkt = K >> 5;

    // ---- initial LDG ----
    #pragma unroll
    for (int i = 0; i < ITA; i++) {
        int L = i*T + tid, m = L >> 3, c = L & 7;
        ra[i] = *(const float4*)&A[(size_t)(br+m)*K + c*4];
    }
    #pragma unroll
    for (int i = 0; i < ITB; i++) {
        int L = i*T + tid, k = L / BC, c = L % BC;
        rb[i] = *(const float4*)&Bp[(size_t)k*N + bc + c*4];
    }
    // ---- STS stage 0 ----
    #pragma unroll
    for (int i = 0; i < ITA; i++) {
        int L = i*T + tid, m = L >> 3, c = L & 7;
        uint4 u;
        u.x = f2tf32(ra[i].x); u.y = f2tf32(ra[i].y);
        u.z = f2tf32(ra[i].z); u.w = f2tf32(ra[i].w);
        *(uint4*)&sA[0][m*32 + (c ^ (m&7))*4] = u;
    }
    #pragma unroll
    for (int i = 0; i < ITB; i++) {
        int L = i*T + tid, k = L / BC, c = L % BC;
        uint4 u;
        u.x = f2tf32(rb[i].x); u.y = f2tf32(rb[i].y);
        u.z = f2tf32(rb[i].z); u.w = f2tf32(rb[i].w);
        int cp = (c & ~7) | ((c & 7) ^ ((k & 3) << 1));
        *(uint4*)&sB[0][k*BN + cp*4] = u;
    }
    __syncthreads();

    for (int kt = 0; kt < nkt; kt++) {
        const int st = kt & 1;
        // prefetch next K-tile (overlapped with MMA below)
        if (kt + 1 < nkt) {
            int k0 = (kt + 1) << 5;
            #pragma unroll
            for (int i = 0; i < ITA; i++) {
                int L = i*T + tid, m = L >> 3, c = L & 7;
                ra[i] = *(const float4*)&A[(size_t)(br+m)*K + k0 + c*4];
            }
            #pragma unroll
            for (int i = 0; i < ITB; i++) {
                int L = i*T + tid, k = L / BC, c = L % BC;
                rb[i] = *(const float4*)&Bp[(size_t)(k0+k)*N + bc + c*4];
            }
        }

        const uint32_t* __restrict__ pA = sA[st];
        const uint32_t* __restrict__ pB = sB[st];
        #pragma unroll
        for (int kc = 0; kc < 4; kc++) {
            uint32_t a[2][4], b[4][2];
            #pragma unroll
            for (int im = 0; im < 2; im++) {
                int base = (wm*32 + im*16 + rl)*32 + w;
                int c0 = (kc*2    ) ^ rl;
                int c1 = (kc*2 + 1) ^ rl;
                a[im][0] = pA[base       + c0*4];
                a[im][1] = pA[base + 256 + c0*4];
                a[im][2] = pA[base       + c1*4];
                a[im][3] = pA[base + 256 + c1*4];
            }
            #pragma unroll
            for (int in = 0; in < 4; in++) {
                int row0 = (kc*8 + w)*BN;
                int cp = wn*8 + ((in*2 + (rl>>2)) ^ (w<<1));
                int off = cp*4 + (rl & 3);
                b[in][0] = pB[row0         + off];
                b[in][1] = pB[row0 + 4*BN  + off];
            }
            #pragma unroll
            for (int im = 0; im < 2; im++)
                #pragma unroll
                for (int in = 0; in < 4; in++)
                    mma_tf32(acc[im][in], a[im][0], a[im][1], a[im][2], a[im][3],
                             b[in][0], b[in][1]);
        }

        // store next tile into the other stage
        if (kt + 1 < nkt) {
            const int sn = st ^ 1;
            #pragma unroll
            for (int i = 0; i < ITA; i++) {
                int L = i*T + tid, m = L >> 3, c = L & 7;
                uint4 u;
                u.x = f2tf32(ra[i].x); u.y = f2tf32(ra[i].y);
                u.z = f2tf32(ra[i].z); u.w = f2tf32(ra[i].w);
                *(uint4*)&sA[sn][m*32 + (c ^ (m&7))*4] = u;
            }
            #pragma unroll
            for (int i = 0; i < ITB; i++) {
                int L = i*T + tid, k = L / BC, c = L % BC;
                uint4 u;
                u.x = f2tf32(rb[i].x); u.y = f2tf32(rb[i].y);
                u.z = f2tf32(rb[i].z); u.w = f2tf32(rb[i].w);
                int cp = (c & ~7) | ((c & 7) ^ ((k & 3) << 1));
                *(uint4*)&sB[sn][k*BN + cp*4] = u;
            }
        }
        __syncthreads();
    }

    // ---- epilogue ----
    const int r0 = br + wm*32 + rl;
    const int c0 = bc + wn*32 + w*2;
    #pragma unroll
    for (int im = 0; im < 2; im++) {
        int r = r0 + im*16;
        #pragma unroll
        for (int in = 0; in < 4; in++) {
            int c = c0 + in*8;
            float2 v0 = make_float2(acc[im][in][0], acc[im][in][1]);
            float2 v1 = make_float2(acc[im][in][2], acc[im][in][3]);
            if (bias) {
                float b0 = bias[c], b1 = bias[c+1];
                v0.x += b0; v0.y += b1; v1.x += b0; v1.y += b1;
            }
            if (relu) {
                v0.x = fmaxf(v0.x, 0.f); v0.y = fmaxf(v0.y, 0.f);
                v1.x = fmaxf(v1.x, 0.f); v1.y = fmaxf(v1.y, 0.f);
            }
            *(float2*)&Cp[(size_t)r     * N + c] = v0;
            *(float2*)&Cp[(size_t)(r+8) * N + c] = v1;
        }
    }
}

// single GEMM, 64x64 tiles
static void tgemm64(const float* A, const float* B, const float* bias, float* C,
                    int M, int N, int K, int relu)
{
    Ptrs3 P; P.B[0]=B; P.B[1]=B; P.B[2]=B; P.C[0]=C; P.C[1]=C; P.C[2]=C;
    dim3 grid(N/64, M/64, 1);
    tgemm_kernel<2,2><<<grid, 128>>>(A, P, bias, M, N, K, relu);
}
// batched GEMM over z shared-A, 64x64 tiles
static void tgemm64z(const float* A, Ptrs3 P, int z, int M, int N, int K)
{
    dim3 grid(N/64, M/64, z);
    tgemm_kernel<2,2><<<grid, 128>>>(A, P, nullptr, M, N, K, 0);
}
// single GEMM, 64x128 tiles
static void tgemm128(const float* A, const float* B, const float* bias, float* C,
                     int M, int N, int K, int relu)
{
    Ptrs3 P; P.B[0]=B; P.B[1]=B; P.B[2]=B; P.C[0]=C; P.C[1]=C; P.C[2]=C;
    dim3 grid(N/128, M/64, 1);
    tgemm_kernel<2,4><<<grid, 256>>>(A, P, bias, M, N, K, relu);
}

// ---------------- attention scores: S = QK^T/8 with reference mask (fill 1e-6) ----------------
__global__ void scores_kernel(const float* __restrict__ Q, const float* __restrict__ Kv,
                              float* __restrict__ Sc, const int* __restrict__ valid,
                              int mode)
{
    int bh = blockIdx.z, b = bh / NH, h = bh % NH;
    int i0 = blockIdx.y * 16, j0 = blockIdx.x * 16;
    __shared__ float Qs[16][DH];
    __shared__ float Ks[16][DH+1];
    int tid = threadIdx.y*16 + threadIdx.x;
    for (int idx = tid; idx < 16*DH; idx += 256) {
        int r = idx / DH, d = idx % DH;
        Qs[r][d] = Q [(b*SEQ + i0 + r)*DM + h*DH + d];
        Ks[r][d] = Kv[(b*SEQ + j0 + r)*DM + h*DH + d];
    }
    __syncthreads();
    int i = i0 + threadIdx.y, j = j0 + threadIdx.x;
    float acc = 0.f;
    #pragma unroll
    for (int d = 0; d < DH; d++) acc += Qs[threadIdx.y][d] * Ks[threadIdx.x][d];
    int vld = (mode == 0) ? min(valid[b], i + 1) : valid[b];
    float val = (j >= vld) ? 1e-6f : acc * 0.125f;
    Sc[(bh*SEQ + i)*SEQ + j] = val;
}

// ---------------- row softmax over 256 keys, one warp per row ----------------
__global__ void softmax_kernel(float* __restrict__ Sc)
{
    int warp = threadIdx.x >> 5, lane = threadIdx.x & 31;
    int row = blockIdx.x * 8 + warp;
    float* p = Sc + (size_t)row * SEQ;
    float vals[8];
    float mx = -1e30f;
    #pragma unroll
    for (int t = 0; t < 8; t++) { vals[t] = p[lane + t*32]; mx = fmaxf(mx, vals[t]); }
    #pragma unroll
    for (int o = 16; o; o >>= 1) mx = fmaxf(mx, __shfl_xor_sync(0xffffffffu, mx, o));
    float sum = 0.f;
    #pragma unroll
    for (int t = 0; t < 8; t++) { vals[t] = expf(vals[t] - mx); sum += vals[t]; }
    #pragma unroll
    for (int o = 16; o; o >>= 1) sum += __shfl_xor_sync(0xffffffffu, sum, o);
    float inv = 1.0f / sum;
    #pragma unroll
    for (int t = 0; t < 8; t++) p[lane + t*32] = vals[t] * inv;
}

// ---------------- O = softmax(S) @ V, concat heads into [B,S,DM] ----------------
__global__ void av_kernel(const float* __restrict__ W, const float* __restrict__ Vv,
                          float* __restrict__ O)
{
    int bh = blockIdx.z, b = bh / NH, h = bh % NH;
    int i0 = blockIdx.y * 16, d0 = blockIdx.x * 16;
    __shared__ float Ws[16][17];
    __shared__ float Vs[16][17];
    float acc = 0.f;
    for (int j0 = 0; j0 < SEQ; j0 += 16) {
        Ws[threadIdx.y][threadIdx.x] = W [(size_t)(bh*SEQ + i0 + threadIdx.y)*SEQ + j0 + threadIdx.x];
        Vs[threadIdx.y][threadIdx.x] = Vv[(b*SEQ + j0 + threadIdx.y)*DM + h*DH + d0 + threadIdx.x];
        __syncthreads();
        #pragma unroll
        for (int jj = 0; jj < 16; jj++) acc += Ws[threadIdx.y][jj] * Vs[jj][threadIdx.x];
        __syncthreads();
    }
    O[(b*SEQ + i0 + threadIdx.y)*DM + h*DH + d0 + threadIdx.x] = acc;
}

// ---------------- out = LayerNorm(a + r) * g + be ----------------
__global__ void add_ln_kernel(const float* __restrict__ a, const float* __restrict__ r,
                              const float* __restrict__ g, const float* __restrict__ be,
                              float* __restrict__ out)
{
    int row = blockIdx.x;
    __shared__ float red[256];
    float x[4];
    #pragma unroll
    for (int t = 0; t < 4; t++) {
        int c = threadIdx.x + t*256;
        x[t] = a[row*DM + c] + r[row*DM + c];
    }
    float s = x[0] + x[1] + x[2] + x[3];
    red[threadIdx.x] = s; __syncthreads();
    for (int o = 128; o; o >>= 1) {
        if (threadIdx.x < o) red[threadIdx.x] += red[threadIdx.x + o];
        __syncthreads();
    }
    float mean = red[0] * (1.0f / DM);
    __syncthreads();
    float vs = 0.f;
    #pragma unroll
    for (int t = 0; t < 4; t++) { float d = x[t] - mean; vs += d*d; }
    red[threadIdx.x] = vs; __syncthreads();
    for (int o = 128; o; o >>= 1) {
        if (threadIdx.x < o) red[threadIdx.x] += red[threadIdx.x + o];
        __syncthreads();
    }
    float inv = rsqrtf(red[0] * (1.0f / DM) + 1e-5f);
    #pragma unroll
    for (int t = 0; t < 4; t++) {
        int c = threadIdx.x + t*256;
        out[row*DM + c] = (x[t] - mean) * inv * g[c] + be[c];
    }
}

// ---------------- host orchestration ----------------
extern "C" void kernel_launch(void* const* d_in, const int* in_sizes, int n_in,
                              void* d_out, int out_size)
{
    const int*   X         = (const int*)  d_in[0];
    const int*   dec_valid = (const int*)  d_in[1];
    const float* enc_out   = (const float*)d_in[2];
    const int*   enc_valid = (const int*)  d_in[3];
    const float* emb       = (const float*)d_in[4];
    const float* Wq1 = (const float*)d_in[5];
    const float* Wk1 = (const float*)d_in[6];
    const float* Wv1 = (const float*)d_in[7];
    const float* Wo1 = (const float*)d_in[8];
    const float* Wq2 = (const float*)d_in[9];
    const float* Wk2 = (const float*)d_in[10];
    const float* Wv2 = (const float*)d_in[11];
    const float* Wo2 = (const float*)d_in[12];
    const float* W1  = (const float*)d_in[13];
    const float* W2  = (const float*)d_in[14];
    const float* Wout= (const float*)d_in[15];
    const float* b1  = (const float*)d_in[16];
    const float* b2  = (const float*)d_in[17];
    const float* bout= (const float*)d_in[18];
    const float* ln1g= (const float*)d_in[19];
    const float* ln1b= (const float*)d_in[20];
    const float* ln2g= (const float*)d_in[21];
    const float* ln2b= (const float*)d_in[22];
    const float* ln3g= (const float*)d_in[23];
    const float* ln3b= (const float*)d_in[24];
    float* out = (float*)d_out;

    float *h, *q, *k, *v, *attn, *proj, *y, *y2, *ffn, *ffn2, *sc;
    cudaGetSymbolAddress((void**)&h,    g_h);
    cudaGetSymbolAddress((void**)&q,    g_q);
    cudaGetSymbolAddress((void**)&k,    g_k);
    cudaGetSymbolAddress((void**)&v,    g_v);
    cudaGetSymbolAddress((void**)&attn, g_attn);
    cudaGetSymbolAddress((void**)&proj, g_proj);
    cudaGetSymbolAddress((void**)&y,    g_y);
    cudaGetSymbolAddress((void**)&y2,   g_y2);
    cudaGetSymbolAddress((void**)&ffn,  g_ffn);
    cudaGetSymbolAddress((void**)&ffn2, g_ffn2);
    cudaGetSymbolAddress((void**)&sc,   g_sc);

    embed_kernel<<<ROWS, 256>>>(X, emb, h);

    dim3 sgrid(SEQ/16, SEQ/16, BZ*NH);
    dim3 agrid(DH/16,  SEQ/16, BZ*NH);
    dim3 tb16(16, 16);
    int  smrows = BZ*NH*SEQ/8;

    for (int l = 0; l < NL; l++) {
        const size_t o2 = (size_t)l*DM*DM;
        // ---- self attention: batched QKV projections ----
        {
            Ptrs3 P;
            P.B[0]=Wq1+o2; P.B[1]=Wk1+o2; P.B[2]=Wv1+o2;
            P.C[0]=q;      P.C[1]=k;      P.C[2]=v;
            tgemm64z(h, P, 3, ROWS, DM, DM);
        }
        scores_kernel<<<sgrid, tb16>>>(q, k, sc, dec_valid, 0);
        softmax_kernel<<<smrows, 256>>>(sc);
        av_kernel<<<agrid, tb16>>>(sc, v, attn);
        tgemm64(attn, Wo1+o2, nullptr, proj, ROWS, DM, DM, 0);
        add_ln_kernel<<<ROWS, 256>>>(h, proj, ln1g + l*DM, ln1b + l*DM, y);
        // ---- cross attention ----
        tgemm64(y, Wq2+o2, nullptr, q, ROWS, DM, DM, 0);
        {
            Ptrs3 P;
            P.B[0]=Wk2+o2; P.B[1]=Wv2+o2; P.B[2]=Wv2+o2;
            P.C[0]=k;      P.C[1]=v;      P.C[2]=v;
            tgemm64z(enc_out, P, 2, ROWS, DM, DM);
        }
        scores_kernel<<<sgrid, tb16>>>(q, k, sc, enc_valid, 1);
        softmax_kernel<<<smrows, 256>>>(sc);
        av_kernel<<<agrid, tb16>>>(sc, v, attn);
        tgemm64(attn, Wo2+o2, nullptr, proj, ROWS, DM, DM, 0);
        add_ln_kernel<<<ROWS, 256>>>(y, proj, ln2g + l*DM, ln2b + l*DM, y2);
        // ---- FFN ----
        tgemm128(y2,  W1 + (size_t)l*DM*HID, b1 + l*HID, ffn,  ROWS, HID, DM, 1);
        tgemm64 (ffn, W2 + (size_t)l*HID*DM, b2 + l*DM,  ffn2, ROWS, DM, HID, 0);
        add_ln_kernel<<<ROWS, 256>>>(y2, ffn2, ln3g + l*DM, ln3b + l*DM, h);
    }
    // ---- final vocab projection ----
    tgemm128(h, Wout, bout, out, ROWS, VOCAB, DM, 0);
}

// round 4
// speedup vs baseline: 4.9709x; 1.4057x over previous
#include <cuda_runtime.h>
#include <math.h>
#include <stdint.h>

#define BZ    4
#define SEQ   256
#define DM    1024
#define HID   4096
#define VOCAB 32000
#define NH    16
#define DH    64
#define NL    6
#define ROWS  (BZ*SEQ)   // 1024

// ---------------- scratch (no allocations allowed) ----------------
__device__ float g_h   [ROWS*DM];
__device__ float g_q   [ROWS*DM];
__device__ float g_k   [ROWS*DM];
__device__ float g_v   [ROWS*DM];
__device__ float g_attn[ROWS*DM];
__device__ float g_proj[ROWS*DM];
__device__ float g_y   [ROWS*DM];
__device__ float g_y2  [ROWS*DM];
__device__ float g_ffn [ROWS*HID];
__device__ float g_ffn2[ROWS*DM];
__device__ float g_sc  [BZ*NH*SEQ*SEQ];

struct Ptrs3 {
    const float* B[3];
    float*       C[3];
};

// ---------------- helpers ----------------
__device__ __forceinline__ uint32_t f2tf32(float f) {
    uint32_t r;
    asm("cvt.rna.tf32.f32 %0, %1;" : "=r"(r) : "f"(f));
    return r;
}

__device__ __forceinline__ void mma_tf32(float c[4],
    uint32_t a0, uint32_t a1, uint32_t a2, uint32_t a3,
    uint32_t b0, uint32_t b1)
{
    asm("mma.sync.aligned.m16n8k8.row.col.f32.tf32.tf32.f32 "
        "{%0,%1,%2,%3},{%4,%5,%6,%7},{%8,%9},{%0,%1,%2,%3};"
        : "+f"(c[0]), "+f"(c[1]), "+f"(c[2]), "+f"(c[3])
        : "r"(a0), "r"(a1), "r"(a2), "r"(a3), "r"(b0), "r"(b1));
}

// ---------------- embedding + sinusoidal positional encoding ----------------
__global__ void embed_kernel(const int* __restrict__ X,
                             const float* __restrict__ emb,
                             float* __restrict__ h)
{
    int row = blockIdx.x;          // b*SEQ + s
    int s = row % SEQ;
    int tok = X[row];
    const float scale = 32.0f;     // sqrt(1024)
    const float l2 = 13.28771238f; // log2(10000)
    for (int d = threadIdx.x; d < DM; d += blockDim.x) {
        int j = d & ~1;
        float freq = exp2f(-((float)j / (float)DM) * l2);
        float ang  = (float)s * freq;
        float sn, cs;
        sincosf(ang, &sn, &cs);
        float p = (d & 1) ? cs : sn;
        h[row*DM + d] = emb[tok*DM + d] * scale + p;
    }
}

// ---------------- tf32 tensor-core GEMM (unchanged from round 3) ----------------
template<int WM, int WN>
__global__ void __launch_bounds__(WM*WN*32, (WM*WN == 4) ? 4 : 2)
tgemm_kernel(const float* __restrict__ A, Ptrs3 P,
             const float* __restrict__ bias, int M, int N, int K, int relu)
{
    constexpr int BM  = WM*32;
    constexpr int BN  = WN*32;
    constexpr int T   = WM*WN*32;
    constexpr int ITA = BM*8 / T;
    constexpr int BC  = BN/4;
    constexpr int ITB = 32*BC / T;

    __shared__ __align__(16) uint32_t sA[2][BM*32];
    __shared__ __align__(16) uint32_t sB[2][32*BN];

    const float* __restrict__ Bp = P.B[blockIdx.z];
    float*       __restrict__ Cp = P.C[blockIdx.z];

    const int tid  = threadIdx.x;
    const int br   = blockIdx.y * BM;
    const int bc   = blockIdx.x * BN;
    const int wid  = tid >> 5;
    const int lane = tid & 31;
    const int wm   = wid / WN;
    const int wn   = wid % WN;
    const int rl   = lane >> 2;
    const int w    = lane & 3;

    float acc[2][4][4];
    #pragma unroll
    for (int im = 0; im < 2; im++)
        #pragma unroll
        for (int in = 0; in < 4; in++)
            #pragma unroll
            for (int t = 0; t < 4; t++) acc[im][in][t] = 0.f;

    float4 ra[ITA], rb[ITB];

    const int nkt = K >> 5;

    #pragma unroll
    for (int i = 0; i < ITA; i++) {
        int L = i*T + tid, m = L >> 3, c = L & 7;
        ra[i] = *(const float4*)&A[(size_t)(br+m)*K + c*4];
    }
    #pragma unroll
    for (int i = 0; i < ITB; i++) {
        int L = i*T + tid, k = L / BC, c = L % BC;
        rb[i] = *(const float4*)&Bp[(size_t)k*N + bc + c*4];
    }
    #pragma unroll
    for (int i = 0; i < ITA; i++) {
        int L = i*T + tid, m = L >> 3, c = L & 7;
        uint4 u;
        u.x = f2tf32(ra[i].x); u.y = f2tf32(ra[i].y);
        u.z = f2tf32(ra[i].z); u.w = f2tf32(ra[i].w);
        *(uint4*)&sA[0][m*32 + (c ^ (m&7))*4] = u;
    }
    #pragma unroll
    for (int i = 0; i < ITB; i++) {
        int L = i*T + tid, k = L / BC, c = L % BC;
        uint4 u;
        u.x = f2tf32(rb[i].x); u.y = f2tf32(rb[i].y);
        u.z = f2tf32(rb[i].z); u.w = f2tf32(rb[i].w);
        int cp = (c & ~7) | ((c & 7) ^ ((k & 3) << 1));
        *(uint4*)&sB[0][k*BN + cp*4] = u;
    }
    __syncthreads();

    for (int kt = 0; kt < nkt; kt++) {
        const int st = kt & 1;
        if (kt + 1 < nkt) {
            int k0 = (kt + 1) << 5;
            #pragma unroll
            for (int i = 0; i < ITA; i++) {
                int L = i*T + tid, m = L >> 3, c = L & 7;
                ra[i] = *(const float4*)&A[(size_t)(br+m)*K + k0 + c*4];
            }
            #pragma unroll
            for (int i = 0; i < ITB; i++) {
                int L = i*T + tid, k = L / BC, c = L % BC;
                rb[i] = *(const float4*)&Bp[(size_t)(k0+k)*N + bc + c*4];
            }
        }

        const uint32_t* __restrict__ pA = sA[st];
        const uint32_t* __restrict__ pB = sB[st];
        #pragma unroll
        for (int kc = 0; kc < 4; kc++) {
            uint32_t a[2][4], b[4][2];
            #pragma unroll
            for (int im = 0; im < 2; im++) {
                int base = (wm*32 + im*16 + rl)*32 + w;
                int c0 = (kc*2    ) ^ rl;
                int c1 = (kc*2 + 1) ^ rl;
                a[im][0] = pA[base       + c0*4];
                a[im][1] = pA[base + 256 + c0*4];
                a[im][2] = pA[base       + c1*4];
                a[im][3] = pA[base + 256 + c1*4];
            }
            #pragma unroll
            for (int in = 0; in < 4; in++) {
                int row0 = (kc*8 + w)*BN;
                int cp = wn*8 + ((in*2 + (rl>>2)) ^ (w<<1));
                int off = cp*4 + (rl & 3);
                b[in][0] = pB[row0         + off];
                b[in][1] = pB[row0 + 4*BN  + off];
            }
            #pragma unroll
            for (int im = 0; im < 2; im++)
                #pragma unroll
                for (int in = 0; in < 4; in++)
                    mma_tf32(acc[im][in], a[im][0], a[im][1], a[im][2], a[im][3],
                             b[in][0], b[in][1]);
        }

        if (kt + 1 < nkt) {
            const int sn = st ^ 1;
            #pragma unroll
            for (int i = 0; i < ITA; i++) {
                int L = i*T + tid, m = L >> 3, c = L & 7;
                uint4 u;
                u.x = f2tf32(ra[i].x); u.y = f2tf32(ra[i].y);
                u.z = f2tf32(ra[i].z); u.w = f2tf32(ra[i].w);
                *(uint4*)&sA[sn][m*32 + (c ^ (m&7))*4] = u;
            }
            #pragma unroll
            for (int i = 0; i < ITB; i++) {
                int L = i*T + tid, k = L / BC, c = L % BC;
                uint4 u;
                u.x = f2tf32(rb[i].x); u.y = f2tf32(rb[i].y);
                u.z = f2tf32(rb[i].z); u.w = f2tf32(rb[i].w);
                int cp = (c & ~7) | ((c & 7) ^ ((k & 3) << 1));
                *(uint4*)&sB[sn][k*BN + cp*4] = u;
            }
        }
        __syncthreads();
    }

    const int r0 = br + wm*32 + rl;
    const int c0 = bc + wn*32 + w*2;
    #pragma unroll
    for (int im = 0; im < 2; im++) {
        int r = r0 + im*16;
        #pragma unroll
        for (int in = 0; in < 4; in++) {
            int c = c0 + in*8;
            float2 v0 = make_float2(acc[im][in][0], acc[im][in][1]);
            float2 v1 = make_float2(acc[im][in][2], acc[im][in][3]);
            if (bias) {
                float b0 = bias[c], b1 = bias[c+1];
                v0.x += b0; v0.y += b1; v1.x += b0; v1.y += b1;
            }
            if (relu) {
                v0.x = fmaxf(v0.x, 0.f); v0.y = fmaxf(v0.y, 0.f);
                v1.x = fmaxf(v1.x, 0.f); v1.y = fmaxf(v1.y, 0.f);
            }
            *(float2*)&Cp[(size_t)r     * N + c] = v0;
            *(float2*)&Cp[(size_t)(r+8) * N + c] = v1;
        }
    }
}

static void tgemm64(const float* A, const float* B, const float* bias, float* C,
                    int M, int N, int K, int relu)
{
    Ptrs3 P; P.B[0]=B; P.B[1]=B; P.B[2]=B; P.C[0]=C; P.C[1]=C; P.C[2]=C;
    dim3 grid(N/64, M/64, 1);
    tgemm_kernel<2,2><<<grid, 128>>>(A, P, bias, M, N, K, relu);
}
static void tgemm64z(const float* A, Ptrs3 P, int z, int M, int N, int K)
{
    dim3 grid(N/64, M/64, z);
    tgemm_kernel<2,2><<<grid, 128>>>(A, P, nullptr, M, N, K, 0);
}
static void tgemm128(const float* A, const float* B, const float* bias, float* C,
                     int M, int N, int K, int relu)
{
    Ptrs3 P; P.B[0]=B; P.B[1]=B; P.B[2]=B; P.C[0]=C; P.C[1]=C; P.C[2]=C;
    dim3 grid(N/128, M/64, 1);
    tgemm_kernel<2,4><<<grid, 256>>>(A, P, bias, M, N, K, relu);
}

// ---------------- tensor-core attention scores ----------------
// S[64x64 tile] = Q_tile @ K_tile^T / 8, mask fill 1e-6 (reference semantics).
// 128 threads (4 warps), each warp 16 q-rows x 64 keys.
#define PS 68   // padded smem row stride (floats)
__global__ void __launch_bounds__(128)
scores_mma_kernel(const float* __restrict__ Q, const float* __restrict__ Kv,
                  float* __restrict__ Sc, const int* __restrict__ valid,
                  int mode)
{
    __shared__ __align__(16) uint32_t Qs[64*PS];
    __shared__ __align__(16) uint32_t Ks[64*PS];

    const int bh = blockIdx.z, b = bh >> 4, h = bh & 15;
    const int i0 = blockIdx.y * 64, j0 = blockIdx.x * 64;
    const int tid = threadIdx.x;
    const int wid = tid >> 5, lane = tid & 31;
    const int rl = lane >> 2, w = lane & 3;
    const int wq = wid * 16;

    // load Q,K tiles (cvt to tf32), uint4 stores (stride 68*4B = 272B, 16B-aligned)
    for (int t = tid; t < 64*16; t += 128) {
        int r = t >> 4, c4 = t & 15;
        float4 fq = *(const float4*)&Q [(size_t)(b*SEQ + i0 + r)*DM + h*DH + c4*4];
        float4 fk = *(const float4*)&Kv[(size_t)(b*SEQ + j0 + r)*DM + h*DH + c4*4];
        uint4 uq, uk;
        uq.x = f2tf32(fq.x); uq.y = f2tf32(fq.y); uq.z = f2tf32(fq.z); uq.w = f2tf32(fq.w);
        uk.x = f2tf32(fk.x); uk.y = f2tf32(fk.y); uk.z = f2tf32(fk.z); uk.w = f2tf32(fk.w);
        *(uint4*)&Qs[r*PS + c4*4] = uq;
        *(uint4*)&Ks[r*PS + c4*4] = uk;
    }
    __syncthreads();

    float acc[8][4];
    #pragma unroll
    for (int nt = 0; nt < 8; nt++)
        #pragma unroll
        for (int t = 0; t < 4; t++) acc[nt][t] = 0.f;

    #pragma unroll
    for (int kk = 0; kk < 8; kk++) {
        int k0 = kk * 8;
        uint32_t a0 = Qs[(wq + rl     )*PS + k0 + w];
        uint32_t a1 = Qs[(wq + rl + 8 )*PS + k0 + w];
        uint32_t a2 = Qs[(wq + rl     )*PS + k0 + w + 4];
        uint32_t a3 = Qs[(wq + rl + 8 )*PS + k0 + w + 4];
        #pragma unroll
        for (int nt = 0; nt < 8; nt++) {
            uint32_t b0 = Ks[(nt*8 + rl)*PS + k0 + w];
            uint32_t b1 = Ks[(nt*8 + rl)*PS + k0 + w + 4];
            mma_tf32(acc[nt], a0, a1, a2, a3, b0, b1);
        }
    }

    // epilogue: scale + reference mask, store
    const int vb = valid[b];
    const int iA = i0 + wq + rl;
    const int iB = iA + 8;
    const int vldA = (mode == 0) ? min(vb, iA + 1) : vb;
    const int vldB = (mode == 0) ? min(vb, iB + 1) : vb;
    #pragma unroll
    for (int nt = 0; nt < 8; nt++) {
        int j = j0 + nt*8 + w*2;
        float2 v0, v1;
        v0.x = (j     >= vldA) ? 1e-6f : acc[nt][0]*0.125f;
        v0.y = (j + 1 >= vldA) ? 1e-6f : acc[nt][1]*0.125f;
        v1.x = (j     >= vldB) ? 1e-6f : acc[nt][2]*0.125f;
        v1.y = (j + 1 >= vldB) ? 1e-6f : acc[nt][3]*0.125f;
        *(float2*)&Sc[(size_t)(bh*SEQ + iA)*SEQ + j] = v0;
        *(float2*)&Sc[(size_t)(bh*SEQ + iB)*SEQ + j] = v1;
    }
}

// ---------------- row softmax over 256 keys, one warp per row ----------------
__global__ void softmax_kernel(float* __restrict__ Sc)
{
    int warp = threadIdx.x >> 5, lane = threadIdx.x & 31;
    int row = blockIdx.x * 8 + warp;
    float* p = Sc + (size_t)row * SEQ;
    float vals[8];
    float mx = -1e30f;
    #pragma unroll
    for (int t = 0; t < 8; t++) { vals[t] = p[lane + t*32]; mx = fmaxf(mx, vals[t]); }
    #pragma unroll
    for (int o = 16; o; o >>= 1) mx = fmaxf(mx, __shfl_xor_sync(0xffffffffu, mx, o));
    float sum = 0.f;
    #pragma unroll
    for (int t = 0; t < 8; t++) { vals[t] = expf(vals[t] - mx); sum += vals[t]; }
    #pragma unroll
    for (int o = 16; o; o >>= 1) sum += __shfl_xor_sync(0xffffffffu, sum, o);
    float inv = 1.0f / sum;
    #pragma unroll
    for (int t = 0; t < 8; t++) p[lane + t*32] = vals[t] * inv;
}

// ---------------- tensor-core O = P @ V, concat heads ----------------
// CTA: 128 thr, out tile 64(q) x 64(dh) per (b,h). V transposed in smem with
// XOR swizzle ((d>>2)&15) on key index for conflict-free STS+LDS.
__global__ void __launch_bounds__(128)
av_mma_kernel(const float* __restrict__ W, const float* __restrict__ Vv,
              float* __restrict__ O)
{
    __shared__ __align__(16) uint32_t Ws [64*PS];  // [q][key]
    __shared__           uint32_t Vst[64*PS];      // [dim][key^f(dim)]

    const int bh = blockIdx.y, b = bh >> 4, h = bh & 15;
    const int i0 = blockIdx.x * 64;
    const int tid = threadIdx.x;
    const int wid = tid >> 5, lane = tid & 31;
    const int rl = lane >> 2, w = lane & 3;
    const int wq = wid * 16;

    float acc[8][4];
    #pragma unroll
    for (int nt = 0; nt < 8; nt++)
        #pragma unroll
        for (int t = 0; t < 4; t++) acc[nt][t] = 0.f;

    for (int j0 = 0; j0 < SEQ; j0 += 64) {
        // W tile: rows q, cols key
        for (int t = tid; t < 64*16; t += 128) {
            int r = t >> 4, c4 = t & 15;
            float4 f = *(const float4*)&W[(size_t)(bh*SEQ + i0 + r)*SEQ + j0 + c4*4];
            uint4 u;
            u.x = f2tf32(f.x); u.y = f2tf32(f.y); u.z = f2tf32(f.z); u.w = f2tf32(f.w);
            *(uint4*)&Ws[r*PS + c4*4] = u;
        }
        // V tile transposed: Vst[d][ j ^ ((d>>2)&15) ]
        for (int t = tid; t < 64*16; t += 128) {
            int j = t >> 4, c4 = t & 15;
            float4 f = *(const float4*)&Vv[(size_t)(b*SEQ + j0 + j)*DM + h*DH + c4*4];
            int d0 = c4*4;
            Vst[(d0  )*PS + (j ^ (((d0  )>>2)&15))] = f2tf32(f.x);
            Vst[(d0+1)*PS + (j ^ (((d0+1)>>2)&15))] = f2tf32(f.y);
            Vst[(d0+2)*PS + (j ^ (((d0+2)>>2)&15))] = f2tf32(f.z);
            Vst[(d0+3)*PS + (j ^ (((d0+3)>>2)&15))] = f2tf32(f.w);
        }
        __syncthreads();

        #pragma unroll
        for (int kk = 0; kk < 8; kk++) {
            int k0 = kk * 8;
            uint32_t a0 = Ws[(wq + rl    )*PS + k0 + w];
            uint32_t a1 = Ws[(wq + rl + 8)*PS + k0 + w];
            uint32_t a2 = Ws[(wq + rl    )*PS + k0 + w + 4];
            uint32_t a3 = Ws[(wq + rl + 8)*PS + k0 + w + 4];
            #pragma unroll
            for (int nt = 0; nt < 8; nt++) {
                int d  = nt*8 + rl;
                int fx = (d >> 2) & 15;
                uint32_t b0 = Vst[d*PS + ((k0 + w    ) ^ fx)];
                uint32_t b1 = Vst[d*PS + ((k0 + w + 4) ^ fx)];
                mma_tf32(acc[nt], a0, a1, a2, a3, b0, b1);
            }
        }
        __syncthreads();
    }

    const int iA = i0 + wq + rl;
    #pragma unroll
    for (int nt = 0; nt < 8; nt++) {
        int d = nt*8 + w*2;
        *(float2*)&O[(size_t)(b*SEQ + iA    )*DM + h*DH + d] = make_float2(acc[nt][0], acc[nt][1]);
        *(float2*)&O[(size_t)(b*SEQ + iA + 8)*DM + h*DH + d] = make_float2(acc[nt][2], acc[nt][3]);
    }
}

// ---------------- out = LayerNorm(a + r) * g + be ----------------
__global__ void add_ln_kernel(const float* __restrict__ a, const float* __restrict__ r,
                              const float* __restrict__ g, const float* __restrict__ be,
                              float* __restrict__ out)
{
    int row = blockIdx.x;
    __shared__ float red[256];
    float x[4];
    #pragma unroll
    for (int t = 0; t < 4; t++) {
        int c = threadIdx.x + t*256;
        x[t] = a[row*DM + c] + r[row*DM + c];
    }
    float s = x[0] + x[1] + x[2] + x[3];
    red[threadIdx.x] = s; __syncthreads();
    for (int o = 128; o; o >>= 1) {
        if (threadIdx.x < o) red[threadIdx.x] += red[threadIdx.x + o];
        __syncthreads();
    }
    float mean = red[0] * (1.0f / DM);
    __syncthreads();
    float vs = 0.f;
    #pragma unroll
    for (int t = 0; t < 4; t++) { float d = x[t] - mean; vs += d*d; }
    red[threadIdx.x] = vs; __syncthreads();
    for (int o = 128; o; o >>= 1) {
        if (threadIdx.x < o) red[threadIdx.x] += red[threadIdx.x + o];
        __syncthreads();
    }
    float inv = rsqrtf(red[0] * (1.0f / DM) + 1e-5f);
    #pragma unroll
    for (int t = 0; t < 4; t++) {
        int c = threadIdx.x + t*256;
        out[row*DM + c] = (x[t] - mean) * inv * g[c] + be[c];
    }
}

// ---------------- host orchestration ----------------
extern "C" void kernel_launch(void* const* d_in, const int* in_sizes, int n_in,
                              void* d_out, int out_size)
{
    const int*   X         = (const int*)  d_in[0];
    const int*   dec_valid = (const int*)  d_in[1];
    const float* enc_out   = (const float*)d_in[2];
    const int*   enc_valid = (const int*)  d_in[3];
    const float* emb       = (const float*)d_in[4];
    const float* Wq1 = (const float*)d_in[5];
    const float* Wk1 = (const float*)d_in[6];
    const float* Wv1 = (const float*)d_in[7];
    const float* Wo1 = (const float*)d_in[8];
    const float* Wq2 = (const float*)d_in[9];
    const float* Wk2 = (const float*)d_in[10];
    const float* Wv2 = (const float*)d_in[11];
    const float* Wo2 = (const float*)d_in[12];
    const float* W1  = (const float*)d_in[13];
    const float* W2  = (const float*)d_in[14];
    const float* Wout= (const float*)d_in[15];
    const float* b1  = (const float*)d_in[16];
    const float* b2  = (const float*)d_in[17];
    const float* bout= (const float*)d_in[18];
    const float* ln1g= (const float*)d_in[19];
    const float* ln1b= (const float*)d_in[20];
    const float* ln2g= (const float*)d_in[21];
    const float* ln2b= (const float*)d_in[22];
    const float* ln3g= (const float*)d_in[23];
    const float* ln3b= (const float*)d_in[24];
    float* out = (float*)d_out;

    float *h, *q, *k, *v, *attn, *proj, *y, *y2, *ffn, *ffn2, *sc;
    cudaGetSymbolAddress((void**)&h,    g_h);
    cudaGetSymbolAddress((void**)&q,    g_q);
    cudaGetSymbolAddress((void**)&k,    g_k);
    cudaGetSymbolAddress((void**)&v,    g_v);
    cudaGetSymbolAddress((void**)&attn, g_attn);
    cudaGetSymbolAddress((void**)&proj, g_proj);
    cudaGetSymbolAddress((void**)&y,    g_y);
    cudaGetSymbolAddress((void**)&y2,   g_y2);
    cudaGetSymbolAddress((void**)&ffn,  g_ffn);
    cudaGetSymbolAddress((void**)&ffn2, g_ffn2);
    cudaGetSymbolAddress((void**)&sc,   g_sc);

    embed_kernel<<<ROWS, 256>>>(X, emb, h);

    dim3 sgrid(SEQ/64, SEQ/64, BZ*NH);   // scores: 4x4x64
    dim3 agrid(SEQ/64, BZ*NH);           // av: 4x64
    int  smrows = BZ*NH*SEQ/8;

    for (int l = 0; l < NL; l++) {
        const size_t o2 = (size_t)l*DM*DM;
        // ---- self attention: batched QKV projections ----
        {
            Ptrs3 P;
            P.B[0]=Wq1+o2; P.B[1]=Wk1+o2; P.B[2]=Wv1+o2;
            P.C[0]=q;      P.C[1]=k;      P.C[2]=v;
            tgemm64z(h, P, 3, ROWS, DM, DM);
        }
        scores_mma_kernel<<<sgrid, 128>>>(q, k, sc, dec_valid, 0);
        softmax_kernel<<<smrows, 256>>>(sc);
        av_mma_kernel<<<agrid, 128>>>(sc, v, attn);
        tgemm64(attn, Wo1+o2, nullptr, proj, ROWS, DM, DM, 0);
        add_ln_kernel<<<ROWS, 256>>>(h, proj, ln1g + l*DM, ln1b + l*DM, y);
        // ---- cross attention ----
        tgemm64(y, Wq2+o2, nullptr, q, ROWS, DM, DM, 0);
        {
            Ptrs3 P;
            P.B[0]=Wk2+o2; P.B[1]=Wv2+o2; P.B[2]=Wv2+o2;
            P.C[0]=k;      P.C[1]=v;      P.C[2]=v;
            tgemm64z(enc_out, P, 2, ROWS, DM, DM);
        }
        scores_mma_kernel<<<sgrid, 128>>>(q, k, sc, enc_valid, 1);
        softmax_kernel<<<smrows, 256>>>(sc);
        av_mma_kernel<<<agrid, 128>>>(sc, v, attn);
        tgemm64(attn, Wo2+o2, nullptr, proj, ROWS, DM, DM, 0);
        add_ln_kernel<<<ROWS, 256>>>(y, proj, ln2g + l*DM, ln2b + l*DM, y2);
        // ---- FFN ----
        tgemm128(y2,  W1 + (size_t)l*DM*HID, b1 + l*HID, ffn,  ROWS, HID, DM, 1);
        tgemm64 (ffn, W2 + (size_t)l*HID*DM, b2 + l*DM,  ffn2, ROWS, DM, HID, 0);
        add_ln_kernel<<<ROWS, 256>>>(y2, ffn2, ln3g + l*DM, ln3b + l*DM, h);
    }
    // ---- final vocab projection ----
    tgemm128(h, Wout, bout, out, ROWS, VOCAB, DM, 0);
}

// round 5
// speedup vs baseline: 5.1712x; 1.0403x over previous
#include <cuda_runtime.h>
#include <math.h>
#include <stdint.h>

#define BZ    4
#define SEQ   256
#define DM    1024
#define HID   4096
#define VOCAB 32000
#define NH    16
#define DH    64
#define NL    6
#define ROWS  (BZ*SEQ)   // 1024

// ---------------- scratch (no allocations allowed) ----------------
__device__ float g_h   [ROWS*DM];
__device__ float g_q   [ROWS*DM];
__device__ float g_k   [ROWS*DM];
__device__ float g_v   [ROWS*DM];
__device__ float g_attn[ROWS*DM];
__device__ float g_proj[ROWS*DM];
__device__ float g_y   [ROWS*DM];
__device__ float g_y2  [ROWS*DM];
__device__ float g_ffn [ROWS*HID];
__device__ float g_ffn2[ROWS*DM];
__device__ float g_k2  [NL*ROWS*DM];   // hoisted cross-attn K for all layers
__device__ float g_v2  [NL*ROWS*DM];   // hoisted cross-attn V for all layers

struct PtrsN {
    const float* B[12];
    float*       C[12];
};

// ---------------- helpers ----------------
__device__ __forceinline__ uint32_t f2tf32(float f) {
    uint32_t r;
    asm("cvt.rna.tf32.f32 %0, %1;" : "=r"(r) : "f"(f));
    return r;
}

__device__ __forceinline__ void mma_tf32(float c[4],
    uint32_t a0, uint32_t a1, uint32_t a2, uint32_t a3,
    uint32_t b0, uint32_t b1)
{
    asm("mma.sync.aligned.m16n8k8.row.col.f32.tf32.tf32.f32 "
        "{%0,%1,%2,%3},{%4,%5,%6,%7},{%8,%9},{%0,%1,%2,%3};"
        : "+f"(c[0]), "+f"(c[1]), "+f"(c[2]), "+f"(c[3])
        : "r"(a0), "r"(a1), "r"(a2), "r"(a3), "r"(b0), "r"(b1));
}

// ---------------- embedding + sinusoidal positional encoding ----------------
__global__ void embed_kernel(const int* __restrict__ X,
                             const float* __restrict__ emb,
                             float* __restrict__ h)
{
    int row = blockIdx.x;          // b*SEQ + s
    int s = row % SEQ;
    int tok = X[row];
    const float scale = 32.0f;     // sqrt(1024)
    const float l2 = 13.28771238f; // log2(10000)
    for (int d = threadIdx.x; d < DM; d += blockDim.x) {
        int j = d & ~1;
        float freq = exp2f(-((float)j / (float)DM) * l2);
        float ang  = (float)s * freq;
        float sn, cs;
        sincosf(ang, &sn, &cs);
        float p = (d & 1) ? cs : sn;
        h[row*DM + d] = emb[tok*DM + d] * scale + p;
    }
}

// ---------------- tf32 tensor-core GEMM (layouts unchanged from round 3) ----------------
template<int WM, int WN>
__global__ void __launch_bounds__(WM*WN*32, (WM*WN == 4) ? 4 : 2)
tgemm_kernel(const float* __restrict__ A, PtrsN P,
             const float* __restrict__ bias, int M, int N, int K, int relu)
{
    constexpr int BM  = WM*32;
    constexpr int BN  = WN*32;
    constexpr int T   = WM*WN*32;
    constexpr int ITA = BM*8 / T;
    constexpr int BC  = BN/4;
    constexpr int ITB = 32*BC / T;

    __shared__ __align__(16) uint32_t sA[2][BM*32];
    __shared__ __align__(16) uint32_t sB[2][32*BN];

    const float* __restrict__ Bp = P.B[blockIdx.z];
    float*       __restrict__ Cp = P.C[blockIdx.z];

    const int tid  = threadIdx.x;
    const int br   = blockIdx.y * BM;
    const int bc   = blockIdx.x * BN;
    const int wid  = tid >> 5;
    const int lane = tid & 31;
    const int wm   = wid / WN;
    const int wn   = wid % WN;
    const int rl   = lane >> 2;
    const int w    = lane & 3;

    float acc[2][4][4];
    #pragma unroll
    for (int im = 0; im < 2; im++)
        #pragma unroll
        for (int in = 0; in < 4; in++)
            #pragma unroll
            for (int t = 0; t < 4; t++) acc[im][in][t] = 0.f;

    float4 ra[ITA], rb[ITB];

    const int nkt = K >> 5;

    #pragma unroll
    for (int i = 0; i < ITA; i++) {
        int L = i*T + tid, m = L >> 3, c = L & 7;
        ra[i] = *(const float4*)&A[(size_t)(br+m)*K + c*4];
    }
    #pragma unroll
    for (int i = 0; i < ITB; i++) {
        int L = i*T + tid, k = L / BC, c = L % BC;
        rb[i] = *(const float4*)&Bp[(size_t)k*N + bc + c*4];
    }
    #pragma unroll
    for (int i = 0; i < ITA; i++) {
        int L = i*T + tid, m = L >> 3, c = L & 7;
        uint4 u;
        u.x = f2tf32(ra[i].x); u.y = f2tf32(ra[i].y);
        u.z = f2tf32(ra[i].z); u.w = f2tf32(ra[i].w);
        *(uint4*)&sA[0][m*32 + (c ^ (m&7))*4] = u;
    }
    #pragma unroll
    for (int i = 0; i < ITB; i++) {
        int L = i*T + tid, k = L / BC, c = L % BC;
        uint4 u;
        u.x = f2tf32(rb[i].x); u.y = f2tf32(rb[i].y);
        u.z = f2tf32(rb[i].z); u.w = f2tf32(rb[i].w);
        int cp = (c & ~7) | ((c & 7) ^ ((k & 3) << 1));
        *(uint4*)&sB[0][k*BN + cp*4] = u;
    }
    __syncthreads();

    for (int kt = 0; kt < nkt; kt++) {
        const int st = kt & 1;
        if (kt + 1 < nkt) {
            int k0 = (kt + 1) << 5;
            #pragma unroll
            for (int i = 0; i < ITA; i++) {
                int L = i*T + tid, m = L >> 3, c = L & 7;
                ra[i] = *(const float4*)&A[(size_t)(br+m)*K + k0 + c*4];
            }
            #pragma unroll
            for (int i = 0; i < ITB; i++) {
                int L = i*T + tid, k = L / BC, c = L % BC;
                rb[i] = *(const float4*)&Bp[(size_t)(k0+k)*N + bc + c*4];
            }
        }

        const uint32_t* __restrict__ pA = sA[st];
        const uint32_t* __restrict__ pB = sB[st];
        #pragma unroll
        for (int kc = 0; kc < 4; kc++) {
            uint32_t a[2][4], b[4][2];
            #pragma unroll
            for (int im = 0; im < 2; im++) {
                int base = (wm*32 + im*16 + rl)*32 + w;
                int c0 = (kc*2    ) ^ rl;
                int c1 = (kc*2 + 1) ^ rl;
                a[im][0] = pA[base       + c0*4];
                a[im][1] = pA[base + 256 + c0*4];
                a[im][2] = pA[base       + c1*4];
                a[im][3] = pA[base + 256 + c1*4];
            }
            #pragma unroll
            for (int in = 0; in < 4; in++) {
                int row0 = (kc*8 + w)*BN;
                int cp = wn*8 + ((in*2 + (rl>>2)) ^ (w<<1));
                int off = cp*4 + (rl & 3);
                b[in][0] = pB[row0         + off];
                b[in][1] = pB[row0 + 4*BN  + off];
            }
            #pragma unroll
            for (int im = 0; im < 2; im++)
                #pragma unroll
                for (int in = 0; in < 4; in++)
                    mma_tf32(acc[im][in], a[im][0], a[im][1], a[im][2], a[im][3],
                             b[in][0], b[in][1]);
        }

        if (kt + 1 < nkt) {
            const int sn = st ^ 1;
            #pragma unroll
            for (int i = 0; i < ITA; i++) {
                int L = i*T + tid, m = L >> 3, c = L & 7;
                uint4 u;
                u.x = f2tf32(ra[i].x); u.y = f2tf32(ra[i].y);
                u.z = f2tf32(ra[i].z); u.w = f2tf32(ra[i].w);
                *(uint4*)&sA[sn][m*32 + (c ^ (m&7))*4] = u;
            }
            #pragma unroll
            for (int i = 0; i < ITB; i++) {
                int L = i*T + tid, k = L / BC, c = L % BC;
                uint4 u;
                u.x = f2tf32(rb[i].x); u.y = f2tf32(rb[i].y);
                u.z = f2tf32(rb[i].z); u.w = f2tf32(rb[i].w);
                int cp = (c & ~7) | ((c & 7) ^ ((k & 3) << 1));
                *(uint4*)&sB[sn][k*BN + cp*4] = u;
            }
        }
        __syncthreads();
    }

    const int r0 = br + wm*32 + rl;
    const int c0 = bc + wn*32 + w*2;
    #pragma unroll
    for (int im = 0; im < 2; im++) {
        int r = r0 + im*16;
        #pragma unroll
        for (int in = 0; in < 4; in++) {
            int c = c0 + in*8;
            float2 v0 = make_float2(acc[im][in][0], acc[im][in][1]);
            float2 v1 = make_float2(acc[im][in][2], acc[im][in][3]);
            if (bias) {
                float b0 = bias[c], b1 = bias[c+1];
                v0.x += b0; v0.y += b1; v1.x += b0; v1.y += b1;
            }
            if (relu) {
                v0.x = fmaxf(v0.x, 0.f); v0.y = fmaxf(v0.y, 0.f);
                v1.x = fmaxf(v1.x, 0.f); v1.y = fmaxf(v1.y, 0.f);
            }
            *(float2*)&Cp[(size_t)r     * N + c] = v0;
            *(float2*)&Cp[(size_t)(r+8) * N + c] = v1;
        }
    }
}

static void tgemm64(const float* A, const float* B, const float* bias, float* C,
                    int M, int N, int K, int relu)
{
    PtrsN P; P.B[0]=B; P.C[0]=C;
    dim3 grid(N/64, M/64, 1);
    tgemm_kernel<2,2><<<grid, 128>>>(A, P, bias, M, N, K, relu);
}
static void tgemm64z(const float* A, PtrsN P, int z, int M, int N, int K)
{
    dim3 grid(N/64, M/64, z);
    tgemm_kernel<2,2><<<grid, 128>>>(A, P, nullptr, M, N, K, 0);
}
static void tgemm128(const float* A, const float* B, const float* bias, float* C,
                     int M, int N, int K, int relu)
{
    PtrsN P; P.B[0]=B; P.C[0]=C;
    dim3 grid(N/128, M/64, 1);
    tgemm_kernel<2,4><<<grid, 256>>>(A, P, bias, M, N, K, relu);
}

// ---------------- fused flash attention ----------------
// One CTA = one (b,h) x 64-query tile vs all 256 keys.
// Dynamic smem: Qs[64*PS] tf32, KVs[64*PS] tf32 (K then V chunks), Sc[64*PSC] fp32.
// Scores (QK^T/8 + reference mask fill 1e-6) -> smem, softmax in smem, P@V in regs.
#define PS  68     // padded tile stride (words)
#define PSC 260    // score row stride (floats): bank = 4*rl + col%4 -> conflict-free frags
#define FLASH_SMEM ((2*64*PS + 64*PSC) * 4)

__global__ void __launch_bounds__(128)
flash_attn_kernel(const float* __restrict__ Q, const float* __restrict__ Kv,
                  const float* __restrict__ Vv, float* __restrict__ O,
                  const int* __restrict__ valid, int mode)
{
    extern __shared__ uint32_t sm[];
    uint32_t* Qs  = sm;                 // [64][PS]
    uint32_t* KVs = sm + 64*PS;         // [64][PS]
    float*    Sc  = (float*)(sm + 2*64*PS);  // [64][PSC]

    const int bh = blockIdx.y, b = bh >> 4, h = bh & 15;
    const int i0 = blockIdx.x * 64;
    const int tid = threadIdx.x;
    const int wid = tid >> 5, lane = tid & 31;
    const int rl = lane >> 2, w = lane & 3;
    const int wq = wid * 16;

    // load Q tile (cvt tf32)
    for (int t = tid; t < 64*16; t += 128) {
        int r = t >> 4, c4 = t & 15;
        float4 f = *(const float4*)&Q[(size_t)(b*SEQ + i0 + r)*DM + h*DH + c4*4];
        uint4 u;
        u.x = f2tf32(f.x); u.y = f2tf32(f.y); u.z = f2tf32(f.z); u.w = f2tf32(f.w);
        *(uint4*)&Qs[r*PS + c4*4] = u;
    }

    const int vb = valid[b];
    const int iA = i0 + wq + rl;
    const int iB = iA + 8;
    const int vldA = (mode == 0) ? min(vb, iA + 1) : vb;
    const int vldB = (mode == 0) ? min(vb, iB + 1) : vb;

    // ---- phase 1: scores for all key chunks ----
    for (int j0 = 0; j0 < SEQ; j0 += 64) {
        __syncthreads();
        for (int t = tid; t < 64*16; t += 128) {
            int r = t >> 4, c4 = t & 15;
            float4 f = *(const float4*)&Kv[(size_t)(b*SEQ + j0 + r)*DM + h*DH + c4*4];
            uint4 u;
            u.x = f2tf32(f.x); u.y = f2tf32(f.y); u.z = f2tf32(f.z); u.w = f2tf32(f.w);
            *(uint4*)&KVs[r*PS + c4*4] = u;
        }
        __syncthreads();

        float acc[8][4];
        #pragma unroll
        for (int nt = 0; nt < 8; nt++)
            #pragma unroll
            for (int t = 0; t < 4; t++) acc[nt][t] = 0.f;

        #pragma unroll
        for (int kk = 0; kk < 8; kk++) {
            int k0 = kk * 8;
            uint32_t a0 = Qs[(wq + rl    )*PS + k0 + w];
            uint32_t a1 = Qs[(wq + rl + 8)*PS + k0 + w];
            uint32_t a2 = Qs[(wq + rl    )*PS + k0 + w + 4];
            uint32_t a3 = Qs[(wq + rl + 8)*PS + k0 + w + 4];
            #pragma unroll
            for (int nt = 0; nt < 8; nt++) {
                uint32_t b0 = KVs[(nt*8 + rl)*PS + k0 + w];
                uint32_t b1 = KVs[(nt*8 + rl)*PS + k0 + w + 4];
                mma_tf32(acc[nt], a0, a1, a2, a3, b0, b1);
            }
        }

        // mask + scale, store into smem score rows (warp-private rows)
        #pragma unroll
        for (int nt = 0; nt < 8; nt++) {
            int j = j0 + nt*8 + w*2;
            float2 v0, v1;
            v0.x = (j     >= vldA) ? 1e-6f : acc[nt][0]*0.125f;
            v0.y = (j + 1 >= vldA) ? 1e-6f : acc[nt][1]*0.125f;
            v1.x = (j     >= vldB) ? 1e-6f : acc[nt][2]*0.125f;
            v1.y = (j + 1 >= vldB) ? 1e-6f : acc[nt][3]*0.125f;
            *(float2*)&Sc[(wq + rl    )*PSC + j] = v0;
            *(float2*)&Sc[(wq + rl + 8)*PSC + j] = v1;
        }
    }
    __syncthreads();

    // ---- phase 2: softmax over each warp's 16 rows ----
    for (int rr = 0; rr < 16; rr++) {
        float* p = Sc + (wq + rr)*PSC;
        float vals[8];
        float mx = -1e30f;
        #pragma unroll
        for (int t = 0; t < 8; t++) { vals[t] = p[lane + t*32]; mx = fmaxf(mx, vals[t]); }
        #pragma unroll
        for (int o = 16; o; o >>= 1) mx = fmaxf(mx, __shfl_xor_sync(0xffffffffu, mx, o));
        float sum = 0.f;
        #pragma unroll
        for (int t = 0; t < 8; t++) { vals[t] = expf(vals[t] - mx); sum += vals[t]; }
        #pragma unroll
        for (int o = 16; o; o >>= 1) sum += __shfl_xor_sync(0xffffffffu, sum, o);
        float inv = 1.0f / sum;
        #pragma unroll
        for (int t = 0; t < 8; t++) p[lane + t*32] = vals[t] * inv;
    }

    // ---- phase 3: O = P @ V ----
    float oacc[8][4];
    #pragma unroll
    for (int nt = 0; nt < 8; nt++)
        #pragma unroll
        for (int t = 0; t < 4; t++) oacc[nt][t] = 0.f;

    for (int j0 = 0; j0 < SEQ; j0 += 64) {
        __syncthreads();   // protects KVs reuse + orders softmax stores
        // V chunk transposed: KVs[d][ j ^ ((d>>2)&15) ]
        for (int t = tid; t < 64*16; t += 128) {
            int j = t >> 4, c4 = t & 15;
            float4 f = *(const float4*)&Vv[(size_t)(b*SEQ + j0 + j)*DM + h*DH + c4*4];
            int d0 = c4*4;
            KVs[(d0  )*PS + (j ^ (((d0  )>>2)&15))] = f2tf32(f.x);
            KVs[(d0+1)*PS + (j ^ (((d0+1)>>2)&15))] = f2tf32(f.y);
            KVs[(d0+2)*PS + (j ^ (((d0+2)>>2)&15))] = f2tf32(f.z);
            KVs[(d0+3)*PS + (j ^ (((d0+3)>>2)&15))] = f2tf32(f.w);
        }
        __syncthreads();

        #pragma unroll
        for (int kk = 0; kk < 8; kk++) {
            int k0 = kk * 8;
            uint32_t a0 = f2tf32(Sc[(wq + rl    )*PSC + j0 + k0 + w]);
            uint32_t a1 = f2tf32(Sc[(wq + rl + 8)*PSC + j0 + k0 + w]);
            uint32_t a2 = f2tf32(Sc[(wq + rl    )*PSC + j0 + k0 + w + 4]);
            uint32_t a3 = f2tf32(Sc[(wq + rl + 8)*PSC + j0 + k0 + w + 4]);
            #pragma unroll
            for (int nt = 0; nt < 8; nt++) {
                int d  = nt*8 + rl;
                int fx = (d >> 2) & 15;
                uint32_t b0 = KVs[d*PS + ((k0 + w    ) ^ fx)];
                uint32_t b1 = KVs[d*PS + ((k0 + w + 4) ^ fx)];
                mma_tf32(oacc[nt], a0, a1, a2, a3, b0, b1);
            }
        }
    }

    #pragma unroll
    for (int nt = 0; nt < 8; nt++) {
        int d = nt*8 + w*2;
        *(float2*)&O[(size_t)(b*SEQ + iA)*DM + h*DH + d] = make_float2(oacc[nt][0], oacc[nt][1]);
        *(float2*)&O[(size_t)(b*SEQ + iB)*DM + h*DH + d] = make_float2(oacc[nt][2], oacc[nt][3]);
    }
}

// ---------------- out = LayerNorm(a + r) * g + be ----------------
__global__ void add_ln_kernel(const float* __restrict__ a, const float* __restrict__ r,
                              const float* __restrict__ g, const float* __restrict__ be,
                              float* __restrict__ out)
{
    int row = blockIdx.x;
    __shared__ float red[256];
    float x[4];
    #pragma unroll
    for (int t = 0; t < 4; t++) {
        int c = threadIdx.x + t*256;
        x[t] = a[row*DM + c] + r[row*DM + c];
    }
    float s = x[0] + x[1] + x[2] + x[3];
    red[threadIdx.x] = s; __syncthreads();
    for (int o = 128; o; o >>= 1) {
        if (threadIdx.x < o) red[threadIdx.x] += red[threadIdx.x + o];
        __syncthreads();
    }
    float mean = red[0] * (1.0f / DM);
    __syncthreads();
    float vs = 0.f;
    #pragma unroll
    for (int t = 0; t < 4; t++) { float d = x[t] - mean; vs += d*d; }
    red[threadIdx.x] = vs; __syncthreads();
    for (int o = 128; o; o >>= 1) {
        if (threadIdx.x < o) red[threadIdx.x] += red[threadIdx.x + o];
        __syncthreads();
    }
    float inv = rsqrtf(red[0] * (1.0f / DM) + 1e-5f);
    #pragma unroll
    for (int t = 0; t < 4; t++) {
        int c = threadIdx.x + t*256;
        out[row*DM + c] = (x[t] - mean) * inv * g[c] + be[c];
    }
}

// ---------------- host orchestration ----------------
extern "C" void kernel_launch(void* const* d_in, const int* in_sizes, int n_in,
                              void* d_out, int out_size)
{
    const int*   X         = (const int*)  d_in[0];
    const int*   dec_valid = (const int*)  d_in[1];
    const float* enc_out   = (const float*)d_in[2];
    const int*   enc_valid = (const int*)  d_in[3];
    const float* emb       = (const float*)d_in[4];
    const float* Wq1 = (const float*)d_in[5];
    const float* Wk1 = (const float*)d_in[6];
    const float* Wv1 = (const float*)d_in[7];
    const float* Wo1 = (const float*)d_in[8];
    const float* Wq2 = (const float*)d_in[9];
    const float* Wk2 = (const float*)d_in[10];
    const float* Wv2 = (const float*)d_in[11];
    const float* Wo2 = (const float*)d_in[12];
    const float* W1  = (const float*)d_in[13];
    const float* W2  = (const float*)d_in[14];
    const float* Wout= (const float*)d_in[15];
    const float* b1  = (const float*)d_in[16];
    const float* b2  = (const float*)d_in[17];
    const float* bout= (const float*)d_in[18];
    const float* ln1g= (const float*)d_in[19];
    const float* ln1b= (const float*)d_in[20];
    const float* ln2g= (const float*)d_in[21];
    const float* ln2b= (const float*)d_in[22];
    const float* ln3g= (const float*)d_in[23];
    const float* ln3b= (const float*)d_in[24];
    float* out = (float*)d_out;

    float *h, *q, *k, *v, *attn, *proj, *y, *y2, *ffn, *ffn2, *k2, *v2;
    cudaGetSymbolAddress((void**)&h,    g_h);
    cudaGetSymbolAddress((void**)&q,    g_q);
    cudaGetSymbolAddress((void**)&k,    g_k);
    cudaGetSymbolAddress((void**)&v,    g_v);
    cudaGetSymbolAddress((void**)&attn, g_attn);
    cudaGetSymbolAddress((void**)&proj, g_proj);
    cudaGetSymbolAddress((void**)&y,    g_y);
    cudaGetSymbolAddress((void**)&y2,   g_y2);
    cudaGetSymbolAddress((void**)&ffn,  g_ffn);
    cudaGetSymbolAddress((void**)&ffn2, g_ffn2);
    cudaGetSymbolAddress((void**)&k2,   g_k2);
    cudaGetSymbolAddress((void**)&v2,   g_v2);

    static int smem_set = 0;
    if (!smem_set) {
        cudaFuncSetAttribute(flash_attn_kernel,
                             cudaFuncAttributeMaxDynamicSharedMemorySize, FLASH_SMEM);
        smem_set = 1;
    }

    embed_kernel<<<ROWS, 256>>>(X, emb, h);

    // hoisted cross-attention K/V projections for ALL layers (enc_out is constant)
    {
        PtrsN P;
        for (int l = 0; l < NL; l++) {
            P.B[l*2  ] = Wk2 + (size_t)l*DM*DM;
            P.B[l*2+1] = Wv2 + (size_t)l*DM*DM;
            P.C[l*2  ] = k2 + (size_t)l*ROWS*DM;
            P.C[l*2+1] = v2 + (size_t)l*ROWS*DM;
        }
        tgemm64z(enc_out, P, 2*NL, ROWS, DM, DM);
    }

    dim3 fgrid(SEQ/64, BZ*NH);

    for (int l = 0; l < NL; l++) {
        const size_t o2 = (size_t)l*DM*DM;
        // ---- self attention ----
        {
            PtrsN P;
            P.B[0]=Wq1+o2; P.B[1]=Wk1+o2; P.B[2]=Wv1+o2;
            P.C[0]=q;      P.C[1]=k;      P.C[2]=v;
            tgemm64z(h, P, 3, ROWS, DM, DM);
        }
        flash_attn_kernel<<<fgrid, 128, FLASH_SMEM>>>(q, k, v, attn, dec_valid, 0);
        tgemm64(attn, Wo1+o2, nullptr, proj, ROWS, DM, DM, 0);
        add_ln_kernel<<<ROWS, 256>>>(h, proj, ln1g + l*DM, ln1b + l*DM, y);
        // ---- cross attention (K/V precomputed) ----
        tgemm64(y, Wq2+o2, nullptr, q, ROWS, DM, DM, 0);
        flash_attn_kernel<<<fgrid, 128, FLASH_SMEM>>>(
            q, k2 + (size_t)l*ROWS*DM, v2 + (size_t)l*ROWS*DM, attn, enc_valid, 1);
        tgemm64(attn, Wo2+o2, nullptr, proj, ROWS, DM, DM, 0);
        add_ln_kernel<<<ROWS, 256>>>(y, proj, ln2g + l*DM, ln2b + l*DM, y2);
        // ---- FFN ----
        tgemm128(y2,  W1 + (size_t)l*DM*HID, b1 + l*HID, ffn,  ROWS, HID, DM, 1);
        tgemm64 (ffn, W2 + (size_t)l*HID*DM, b2 + l*DM,  ffn2, ROWS, DM, HID, 0);
        add_ln_kernel<<<ROWS, 256>>>(y2, ffn2, ln3g + l*DM, ln3b + l*DM, h);
    }
    // ---- final vocab projection ----
    tgemm128(h, Wout, bout, out, ROWS, VOCAB, DM, 0);
}

// round 6
// speedup vs baseline: 5.3470x; 1.0340x over previous
#include <cuda_runtime.h>
#include <math.h>
#include <stdint.h>

#define BZ    4
#define SEQ   256
#define DM    1024
#define HID   4096
#define VOCAB 32000
#define NH    16
#define DH    64
#define NL    6
#define ROWS  (BZ*SEQ)   // 1024

// ---------------- scratch (no allocations allowed) ----------------
__device__ float g_h   [ROWS*DM];
__device__ float g_q   [ROWS*DM];
__device__ float g_k   [ROWS*DM];
__device__ float g_v   [ROWS*DM];
__device__ float g_attn[ROWS*DM];
__device__ float g_proj[ROWS*DM];
__device__ float g_y   [ROWS*DM];
__device__ float g_y2  [ROWS*DM];
__device__ float g_ffn [ROWS*HID];
__device__ float g_ffn2[ROWS*DM];
__device__ float g_k2  [NL*ROWS*DM];   // hoisted cross-attn K for all layers
__device__ float g_v2  [NL*ROWS*DM];   // hoisted cross-attn V for all layers

struct PtrsN {
    const float* B[12];
    float*       C[12];
};

// ---------------- helpers ----------------
__device__ __forceinline__ uint32_t f2tf32(float f) {
    uint32_t r;
    asm("cvt.rna.tf32.f32 %0, %1;" : "=r"(r) : "f"(f));
    return r;
}

__device__ __forceinline__ void mma_tf32(float c[4],
    uint32_t a0, uint32_t a1, uint32_t a2, uint32_t a3,
    uint32_t b0, uint32_t b1)
{
    asm("mma.sync.aligned.m16n8k8.row.col.f32.tf32.tf32.f32 "
        "{%0,%1,%2,%3},{%4,%5,%6,%7},{%8,%9},{%0,%1,%2,%3};"
        : "+f"(c[0]), "+f"(c[1]), "+f"(c[2]), "+f"(c[3])
        : "r"(a0), "r"(a1), "r"(a2), "r"(a3), "r"(b0), "r"(b1));
}

// ---------------- embedding + sinusoidal positional encoding ----------------
__global__ void embed_kernel(const int* __restrict__ X,
                             const float* __restrict__ emb,
                             float* __restrict__ h)
{
    int row = blockIdx.x;          // b*SEQ + s
    int s = row % SEQ;
    int tok = X[row];
    const float scale = 32.0f;     // sqrt(1024)
    const float l2 = 13.28771238f; // log2(10000)
    for (int d = threadIdx.x; d < DM; d += blockDim.x) {
        int j = d & ~1;
        float freq = exp2f(-((float)j / (float)DM) * l2);
        float ang  = (float)s * freq;
        float sn, cs;
        sincosf(ang, &sn, &cs);
        float p = (d & 1) ? cs : sn;
        h[row*DM + d] = emb[tok*DM + d] * scale + p;
    }
}

// ---------------- tf32 tensor-core GEMM ----------------
// Block tile (WM*32)x(WN*32)x32, warp tile 32x32, mma m16n8k8 tf32.
// Dynamic double-buffered SMEM, XOR swizzles (verified in rounds 3-5).
// MX=1: M-tiles on blockIdx.x (consecutive CTAs share a B band -> L2 reuse).
template<int WM, int WN, int MX>
__global__ void __launch_bounds__(WM*WN*32, (WM*WN == 4) ? 4 : ((WM*WN == 8) ? 2 : 1))
tgemm_kernel(const float* __restrict__ A, PtrsN P,
             const float* __restrict__ bias, int M, int N, int K, int relu)
{
    constexpr int BM  = WM*32;
    constexpr int BN  = WN*32;
    constexpr int T   = WM*WN*32;
    constexpr int ITA = BM*8 / T;
    constexpr int BC  = BN/4;
    constexpr int ITB = 32*BC / T;
    constexpr int SZA = BM*32;
    constexpr int SZB = 32*BN;

    extern __shared__ __align__(16) uint32_t smem_u[];
    uint32_t* sA = smem_u;            // [2][SZA]
    uint32_t* sB = smem_u + 2*SZA;    // [2][SZB]

    const float* __restrict__ Bp = P.B[blockIdx.z];
    float*       __restrict__ Cp = P.C[blockIdx.z];

    const int tid  = threadIdx.x;
    const int br   = (MX ? blockIdx.x : blockIdx.y) * BM;
    const int bc   = (MX ? blockIdx.y : blockIdx.x) * BN;
    const int wid  = tid >> 5;
    const int lane = tid & 31;
    const int wm   = wid / WN;
    const int wn   = wid % WN;
    const int rl   = lane >> 2;
    const int w    = lane & 3;

    float acc[2][4][4];
    #pragma unroll
    for (int im = 0; im < 2; im++)
        #pragma unroll
        for (int in = 0; in < 4; in++)
            #pragma unroll
            for (int t = 0; t < 4; t++) acc[im][in][t] = 0.f;

    float4 ra[ITA], rb[ITB];

    const int nkt = K >> 5;

    #pragma unroll
    for (int i = 0; i < ITA; i++) {
        int L = i*T + tid, m = L >> 3, c = L & 7;
        ra[i] = *(const float4*)&A[(size_t)(br+m)*K + c*4];
    }
    #pragma unroll
    for (int i = 0; i < ITB; i++) {
        int L = i*T + tid, k = L / BC, c = L % BC;
        rb[i] = *(const float4*)&Bp[(size_t)k*N + bc + c*4];
    }
    #pragma unroll
    for (int i = 0; i < ITA; i++) {
        int L = i*T + tid, m = L >> 3, c = L & 7;
        uint4 u;
        u.x = f2tf32(ra[i].x); u.y = f2tf32(ra[i].y);
        u.z = f2tf32(ra[i].z); u.w = f2tf32(ra[i].w);
        *(uint4*)&sA[m*32 + (c ^ (m&7))*4] = u;
    }
    #pragma unroll
    for (int i = 0; i < ITB; i++) {
        int L = i*T + tid, k = L / BC, c = L % BC;
        uint4 u;
        u.x = f2tf32(rb[i].x); u.y = f2tf32(rb[i].y);
        u.z = f2tf32(rb[i].z); u.w = f2tf32(rb[i].w);
        int cp = (c & ~7) | ((c & 7) ^ ((k & 3) << 1));
        *(uint4*)&sB[k*BN + cp*4] = u;
    }
    __syncthreads();

    for (int kt = 0; kt < nkt; kt++) {
        const int st = kt & 1;
        if (kt + 1 < nkt) {
            int k0 = (kt + 1) << 5;
            #pragma unroll
            for (int i = 0; i < ITA; i++) {
                int L = i*T + tid, m = L >> 3, c = L & 7;
                ra[i] = *(const float4*)&A[(size_t)(br+m)*K + k0 + c*4];
            }
            #pragma unroll
            for (int i = 0; i < ITB; i++) {
                int L = i*T + tid, k = L / BC, c = L % BC;
                rb[i] = *(const float4*)&Bp[(size_t)(k0+k)*N + bc + c*4];
            }
        }

        const uint32_t* __restrict__ pA = sA + st*SZA;
        const uint32_t* __restrict__ pB = sB + st*SZB;
        #pragma unroll
        for (int kc = 0; kc < 4; kc++) {
            uint32_t a[2][4], b[4][2];
            #pragma unroll
            for (int im = 0; im < 2; im++) {
                int base = (wm*32 + im*16 + rl)*32 + w;
                int c0 = (kc*2    ) ^ rl;
                int c1 = (kc*2 + 1) ^ rl;
                a[im][0] = pA[base       + c0*4];
                a[im][1] = pA[base + 256 + c0*4];
                a[im][2] = pA[base       + c1*4];
                a[im][3] = pA[base + 256 + c1*4];
            }
            #pragma unroll
            for (int in = 0; in < 4; in++) {
                int row0 = (kc*8 + w)*BN;
                int cp = wn*8 + ((in*2 + (rl>>2)) ^ (w<<1));
                int off = cp*4 + (rl & 3);
                b[in][0] = pB[row0         + off];
                b[in][1] = pB[row0 + 4*BN  + off];
            }
            #pragma unroll
            for (int im = 0; im < 2; im++)
                #pragma unroll
                for (int in = 0; in < 4; in++)
                    mma_tf32(acc[im][in], a[im][0], a[im][1], a[im][2], a[im][3],
                             b[in][0], b[in][1]);
        }

        if (kt + 1 < nkt) {
            const int sn = st ^ 1;
            #pragma unroll
            for (int i = 0; i < ITA; i++) {
                int L = i*T + tid, m = L >> 3, c = L & 7;
                uint4 u;
                u.x = f2tf32(ra[i].x); u.y = f2tf32(ra[i].y);
                u.z = f2tf32(ra[i].z); u.w = f2tf32(ra[i].w);
                *(uint4*)&sA[sn*SZA + m*32 + (c ^ (m&7))*4] = u;
            }
            #pragma unroll
            for (int i = 0; i < ITB; i++) {
                int L = i*T + tid, k = L / BC, c = L % BC;
                uint4 u;
                u.x = f2tf32(rb[i].x); u.y = f2tf32(rb[i].y);
                u.z = f2tf32(rb[i].z); u.w = f2tf32(rb[i].w);
                int cp = (c & ~7) | ((c & 7) ^ ((k & 3) << 1));
                *(uint4*)&sB[sn*SZB + k*BN + cp*4] = u;
            }
        }
        __syncthreads();
    }

    const int r0 = br + wm*32 + rl;
    const int c0 = bc + wn*32 + w*2;
    #pragma unroll
    for (int im = 0; im < 2; im++) {
        int r = r0 + im*16;
        #pragma unroll
        for (int in = 0; in < 4; in++) {
            int c = c0 + in*8;
            float2 v0 = make_float2(acc[im][in][0], acc[im][in][1]);
            float2 v1 = make_float2(acc[im][in][2], acc[im][in][3]);
            if (bias) {
                float b0 = bias[c], b1 = bias[c+1];
                v0.x += b0; v0.y += b1; v1.x += b0; v1.y += b1;
            }
            if (relu) {
                v0.x = fmaxf(v0.x, 0.f); v0.y = fmaxf(v0.y, 0.f);
                v1.x = fmaxf(v1.x, 0.f); v1.y = fmaxf(v1.y, 0.f);
            }
            *(float2*)&Cp[(size_t)r     * N + c] = v0;
            *(float2*)&Cp[(size_t)(r+8) * N + c] = v1;
        }
    }
}

#define SMEM_22 ((2*64*32  + 2*32*64 ) * 4)   // 32 KB
#define SMEM_44 ((2*128*32 + 2*32*128) * 4)   // 64 KB

static void tgemm64(const float* A, const float* B, const float* bias, float* C,
                    int M, int N, int K, int relu)
{
    PtrsN P; P.B[0]=B; P.C[0]=C;
    dim3 grid(N/64, M/64, 1);
    tgemm_kernel<2,2,0><<<grid, 128, SMEM_22>>>(A, P, bias, M, N, K, relu);
}
// big-tile 128x128, M-fastest grid, z-batched
static void tgemm_big(const float* A, PtrsN P, const float* bias, int z,
                      int M, int N, int K, int relu)
{
    dim3 grid(M/128, N/128, z);
    tgemm_kernel<4,4,1><<<grid, 512, SMEM_44>>>(A, P, bias, M, N, K, relu);
}

// ---------------- fused flash attention (unchanged from round 5) ----------------
#define PS  68
#define PSC 260
#define FLASH_SMEM ((2*64*PS + 64*PSC) * 4)

__global__ void __launch_bounds__(128)
flash_attn_kernel(const float* __restrict__ Q, const float* __restrict__ Kv,
                  const float* __restrict__ Vv, float* __restrict__ O,
                  const int* __restrict__ valid, int mode)
{
    extern __shared__ uint32_t sm[];
    uint32_t* Qs  = sm;
    uint32_t* KVs = sm + 64*PS;
    float*    Sc  = (float*)(sm + 2*64*PS);

    const int bh = blockIdx.y, b = bh >> 4, h = bh & 15;
    const int i0 = blockIdx.x * 64;
    const int tid = threadIdx.x;
    const int wid = tid >> 5, lane = tid & 31;
    const int rl = lane >> 2, w = lane & 3;
    const int wq = wid * 16;

    for (int t = tid; t < 64*16; t += 128) {
        int r = t >> 4, c4 = t & 15;
        float4 f = *(const float4*)&Q[(size_t)(b*SEQ + i0 + r)*DM + h*DH + c4*4];
        uint4 u;
        u.x = f2tf32(f.x); u.y = f2tf32(f.y); u.z = f2tf32(f.z); u.w = f2tf32(f.w);
        *(uint4*)&Qs[r*PS + c4*4] = u;
    }

    const int vb = valid[b];
    const int iA = i0 + wq + rl;
    const int iB = iA + 8;
    const int vldA = (mode == 0) ? min(vb, iA + 1) : vb;
    const int vldB = (mode == 0) ? min(vb, iB + 1) : vb;

    for (int j0 = 0; j0 < SEQ; j0 += 64) {
        __syncthreads();
        for (int t = tid; t < 64*16; t += 128) {
            int r = t >> 4, c4 = t & 15;
            float4 f = *(const float4*)&Kv[(size_t)(b*SEQ + j0 + r)*DM + h*DH + c4*4];
            uint4 u;
            u.x = f2tf32(f.x); u.y = f2tf32(f.y); u.z = f2tf32(f.z); u.w = f2tf32(f.w);
            *(uint4*)&KVs[r*PS + c4*4] = u;
        }
        __syncthreads();

        float acc[8][4];
        #pragma unroll
        for (int nt = 0; nt < 8; nt++)
            #pragma unroll
            for (int t = 0; t < 4; t++) acc[nt][t] = 0.f;

        #pragma unroll
        for (int kk = 0; kk < 8; kk++) {
            int k0 = kk * 8;
            uint32_t a0 = Qs[(wq + rl    )*PS + k0 + w];
            uint32_t a1 = Qs[(wq + rl + 8)*PS + k0 + w];
            uint32_t a2 = Qs[(wq + rl    )*PS + k0 + w + 4];
            uint32_t a3 = Qs[(wq + rl + 8)*PS + k0 + w + 4];
            #pragma unroll
            for (int nt = 0; nt < 8; nt++) {
                uint32_t b0 = KVs[(nt*8 + rl)*PS + k0 + w];
                uint32_t b1 = KVs[(nt*8 + rl)*PS + k0 + w + 4];
                mma_tf32(acc[nt], a0, a1, a2, a3, b0, b1);
            }
        }

        #pragma unroll
        for (int nt = 0; nt < 8; nt++) {
            int j = j0 + nt*8 + w*2;
            float2 v0, v1;
            v0.x = (j     >= vldA) ? 1e-6f : acc[nt][0]*0.125f;
            v0.y = (j + 1 >= vldA) ? 1e-6f : acc[nt][1]*0.125f;
            v1.x = (j     >= vldB) ? 1e-6f : acc[nt][2]*0.125f;
            v1.y = (j + 1 >= vldB) ? 1e-6f : acc[nt][3]*0.125f;
            *(float2*)&Sc[(wq + rl    )*PSC + j] = v0;
            *(float2*)&Sc[(wq + rl + 8)*PSC + j] = v1;
        }
    }
    __syncthreads();

    for (int rr = 0; rr < 16; rr++) {
        float* p = Sc + (wq + rr)*PSC;
        float vals[8];
        float mx = -1e30f;
        #pragma unroll
        for (int t = 0; t < 8; t++) { vals[t] = p[lane + t*32]; mx = fmaxf(mx, vals[t]); }
        #pragma unroll
        for (int o = 16; o; o >>= 1) mx = fmaxf(mx, __shfl_xor_sync(0xffffffffu, mx, o));
        float sum = 0.f;
        #pragma unroll
        for (int t = 0; t < 8; t++) { vals[t] = expf(vals[t] - mx); sum += vals[t]; }
        #pragma unroll
        for (int o = 16; o; o >>= 1) sum += __shfl_xor_sync(0xffffffffu, sum, o);
        float inv = 1.0f / sum;
        #pragma unroll
        for (int t = 0; t < 8; t++) p[lane + t*32] = vals[t] * inv;
    }

    float oacc[8][4];
    #pragma unroll
    for (int nt = 0; nt < 8; nt++)
        #pragma unroll
        for (int t = 0; t < 4; t++) oacc[nt][t] = 0.f;

    for (int j0 = 0; j0 < SEQ; j0 += 64) {
        __syncthreads();
        for (int t = tid; t < 64*16; t += 128) {
            int j = t >> 4, c4 = t & 15;
            float4 f = *(const float4*)&Vv[(size_t)(b*SEQ + j0 + j)*DM + h*DH + c4*4];
            int d0 = c4*4;
            KVs[(d0  )*PS + (j ^ (((d0  )>>2)&15))] = f2tf32(f.x);
            KVs[(d0+1)*PS + (j ^ (((d0+1)>>2)&15))] = f2tf32(f.y);
            KVs[(d0+2)*PS + (j ^ (((d0+2)>>2)&15))] = f2tf32(f.z);
            KVs[(d0+3)*PS + (j ^ (((d0+3)>>2)&15))] = f2tf32(f.w);
        }
        __syncthreads();

        #pragma unroll
        for (int kk = 0; kk < 8; kk++) {
            int k0 = kk * 8;
            uint32_t a0 = f2tf32(Sc[(wq + rl    )*PSC + j0 + k0 + w]);
            uint32_t a1 = f2tf32(Sc[(wq + rl + 8)*PSC + j0 + k0 + w]);
            uint32_t a2 = f2tf32(Sc[(wq + rl    )*PSC + j0 + k0 + w + 4]);
            uint32_t a3 = f2tf32(Sc[(wq + rl + 8)*PSC + j0 + k0 + w + 4]);
            #pragma unroll
            for (int nt = 0; nt < 8; nt++) {
                int d  = nt*8 + rl;
                int fx = (d >> 2) & 15;
                uint32_t b0 = KVs[d*PS + ((k0 + w    ) ^ fx)];
                uint32_t b1 = KVs[d*PS + ((k0 + w + 4) ^ fx)];
                mma_tf32(oacc[nt], a0, a1, a2, a3, b0, b1);
            }
        }
    }

    #pragma unroll
    for (int nt = 0; nt < 8; nt++) {
        int d = nt*8 + w*2;
        *(float2*)&O[(size_t)(b*SEQ + iA)*DM + h*DH + d] = make_float2(oacc[nt][0], oacc[nt][1]);
        *(float2*)&O[(size_t)(b*SEQ + iB)*DM + h*DH + d] = make_float2(oacc[nt][2], oacc[nt][3]);
    }
}

// ---------------- out = LayerNorm(a + r) * g + be ----------------
__global__ void add_ln_kernel(const float* __restrict__ a, const float* __restrict__ r,
                              const float* __restrict__ g, const float* __restrict__ be,
                              float* __restrict__ out)
{
    int row = blockIdx.x;
    __shared__ float red[256];
    float x[4];
    #pragma unroll
    for (int t = 0; t < 4; t++) {
        int c = threadIdx.x + t*256;
        x[t] = a[row*DM + c] + r[row*DM + c];
    }
    float s = x[0] + x[1] + x[2] + x[3];
    red[threadIdx.x] = s; __syncthreads();
    for (int o = 128; o; o >>= 1) {
        if (threadIdx.x < o) red[threadIdx.x] += red[threadIdx.x + o];
        __syncthreads();
    }
    float mean = red[0] * (1.0f / DM);
    __syncthreads();
    float vs = 0.f;
    #pragma unroll
    for (int t = 0; t < 4; t++) { float d = x[t] - mean; vs += d*d; }
    red[threadIdx.x] = vs; __syncthreads();
    for (int o = 128; o; o >>= 1) {
        if (threadIdx.x < o) red[threadIdx.x] += red[threadIdx.x + o];
        __syncthreads();
    }
    float inv = rsqrtf(red[0] * (1.0f / DM) + 1e-5f);
    #pragma unroll
    for (int t = 0; t < 4; t++) {
        int c = threadIdx.x + t*256;
        out[row*DM + c] = (x[t] - mean) * inv * g[c] + be[c];
    }
}

// ---------------- host orchestration ----------------
extern "C" void kernel_launch(void* const* d_in, const int* in_sizes, int n_in,
                              void* d_out, int out_size)
{
    const int*   X         = (const int*)  d_in[0];
    const int*   dec_valid = (const int*)  d_in[1];
    const float* enc_out   = (const float*)d_in[2];
    const int*   enc_valid = (const int*)  d_in[3];
    const float* emb       = (const float*)d_in[4];
    const float* Wq1 = (const float*)d_in[5];
    const float* Wk1 = (const float*)d_in[6];
    const float* Wv1 = (const float*)d_in[7];
    const float* Wo1 = (const float*)d_in[8];
    const float* Wq2 = (const float*)d_in[9];
    const float* Wk2 = (const float*)d_in[10];
    const float* Wv2 = (const float*)d_in[11];
    const float* Wo2 = (const float*)d_in[12];
    const float* W1  = (const float*)d_in[13];
    const float* W2  = (const float*)d_in[14];
    const float* Wout= (const float*)d_in[15];
    const float* b1  = (const float*)d_in[16];
    const float* b2  = (const float*)d_in[17];
    const float* bout= (const float*)d_in[18];
    const float* ln1g= (const float*)d_in[19];
    const float* ln1b= (const float*)d_in[20];
    const float* ln2g= (const float*)d_in[21];
    const float* ln2b= (const float*)d_in[22];
    const float* ln3g= (const float*)d_in[23];
    const float* ln3b= (const float*)d_in[24];
    float* out = (float*)d_out;

    float *h, *q, *k, *v, *attn, *proj, *y, *y2, *ffn, *ffn2, *k2, *v2;
    cudaGetSymbolAddress((void**)&h,    g_h);
    cudaGetSymbolAddress((void**)&q,    g_q);
    cudaGetSymbolAddress((void**)&k,    g_k);
    cudaGetSymbolAddress((void**)&v,    g_v);
    cudaGetSymbolAddress((void**)&attn, g_attn);
    cudaGetSymbolAddress((void**)&proj, g_proj);
    cudaGetSymbolAddress((void**)&y,    g_y);
    cudaGetSymbolAddress((void**)&y2,   g_y2);
    cudaGetSymbolAddress((void**)&ffn,  g_ffn);
    cudaGetSymbolAddress((void**)&ffn2, g_ffn2);
    cudaGetSymbolAddress((void**)&k2,   g_k2);
    cudaGetSymbolAddress((void**)&v2,   g_v2);

    static int attr_set = 0;
    if (!attr_set) {
        cudaFuncSetAttribute(flash_attn_kernel,
                             cudaFuncAttributeMaxDynamicSharedMemorySize, FLASH_SMEM);
        cudaFuncSetAttribute(tgemm_kernel<4,4,1>,
                             cudaFuncAttributeMaxDynamicSharedMemorySize, SMEM_44);
        attr_set = 1;
    }

    embed_kernel<<<ROWS, 256>>>(X, emb, h);

    // hoisted cross-attention K/V projections for ALL layers (enc_out is constant)
    {
        PtrsN P;
        for (int l = 0; l < NL; l++) {
            P.B[l*2  ] = Wk2 + (size_t)l*DM*DM;
            P.B[l*2+1] = Wv2 + (size_t)l*DM*DM;
            P.C[l*2  ] = k2 + (size_t)l*ROWS*DM;
            P.C[l*2+1] = v2 + (size_t)l*ROWS*DM;
        }
        tgemm_big(enc_out, P, nullptr, 2*NL, ROWS, DM, DM, 0);
    }

    dim3 fgrid(SEQ/64, BZ*NH);

    for (int l = 0; l < NL; l++) {
        const size_t o2 = (size_t)l*DM*DM;
        // ---- self attention ----
        {
            PtrsN P;
            P.B[0]=Wq1+o2; P.B[1]=Wk1+o2; P.B[2]=Wv1+o2;
            P.C[0]=q;      P.C[1]=k;      P.C[2]=v;
            tgemm_big(h, P, nullptr, 3, ROWS, DM, DM, 0);
        }
        flash_attn_kernel<<<fgrid, 128, FLASH_SMEM>>>(q, k, v, attn, dec_valid, 0);
        tgemm64(attn, Wo1+o2, nullptr, proj, ROWS, DM, DM, 0);
        add_ln_kernel<<<ROWS, 256>>>(h, proj, ln1g + l*DM, ln1b + l*DM, y);
        // ---- cross attention (K/V precomputed) ----
        tgemm64(y, Wq2+o2, nullptr, q, ROWS, DM, DM, 0);
        flash_attn_kernel<<<fgrid, 128, FLASH_SMEM>>>(
            q, k2 + (size_t)l*ROWS*DM, v2 + (size_t)l*ROWS*DM, attn, enc_valid, 1);
        tgemm64(attn, Wo2+o2, nullptr, proj, ROWS, DM, DM, 0);
        add_ln_kernel<<<ROWS, 256>>>(y, proj, ln2g + l*DM, ln2b + l*DM, y2);
        // ---- FFN ----
        {
            PtrsN P;
            P.B[0] = W1 + (size_t)l*DM*HID;
            P.C[0] = ffn;
            tgemm_big(y2, P, b1 + l*HID, 1, ROWS, HID, DM, 1);
        }
        tgemm64(ffn, W2 + (size_t)l*HID*DM, b2 + l*DM, ffn2, ROWS, DM, HID, 0);
        add_ln_kernel<<<ROWS, 256>>>(y2, ffn2, ln3g + l*DM, ln3b + l*DM, h);
    }
    // ---- final vocab projection ----
    {
        PtrsN P;
        P.B[0] = Wout;
        P.C[0] = out;
        tgemm_big(h, P, bout, 1, ROWS, VOCAB, DM, 0);
    }
}

// round 7
// speedup vs baseline: 6.6146x; 1.2371x over previous
#include <cuda_runtime.h>
#include <cuda_fp16.h>
#include <math.h>
#include <stdint.h>

#define BZ    4
#define SEQ   256
#define DM    1024
#define HID   4096
#define VOCAB 32000
#define NH    16
#define DH    64
#define NL    6
#define ROWS  (BZ*SEQ)   // 1024

// ---------------- scratch (no allocations allowed) ----------------
__device__ float g_h   [ROWS*DM];
__device__ float g_q   [ROWS*DM];
__device__ float g_k   [ROWS*DM];
__device__ float g_v   [ROWS*DM];
__device__ float g_attn[ROWS*DM];
__device__ float g_proj[ROWS*DM];
__device__ float g_y   [ROWS*DM];
__device__ float g_y2  [ROWS*DM];
__device__ float g_ffn [ROWS*HID];
__device__ float g_ffn2[ROWS*DM];
__device__ float g_k2  [NL*ROWS*DM];
__device__ float g_v2  [NL*ROWS*DM];

// transposed half weights: [N][K] layout (B^T) for mma .col B operand
__device__ __half g_wq1h[NL*DM*DM];
__device__ __half g_wk1h[NL*DM*DM];
__device__ __half g_wv1h[NL*DM*DM];
__device__ __half g_wo1h[NL*DM*DM];
__device__ __half g_wq2h[NL*DM*DM];
__device__ __half g_wk2h[NL*DM*DM];
__device__ __half g_wv2h[NL*DM*DM];
__device__ __half g_wo2h[NL*DM*DM];
__device__ __half g_w1h [NL*(size_t)HID*DM];
__device__ __half g_w2h [NL*(size_t)DM*HID];
__device__ __half g_wouth[(size_t)VOCAB*DM];

struct PtrsN {
    const __half* B[12];
    float*        C[12];
};

// ---------------- helpers ----------------
__device__ __forceinline__ uint32_t f2tf32(float f) {
    uint32_t r;
    asm("cvt.rna.tf32.f32 %0, %1;" : "=r"(r) : "f"(f));
    return r;
}
__device__ __forceinline__ uint32_t f2h2(float lo, float hi) {
    uint32_t r;
    asm("cvt.rn.f16x2.f32 %0, %1, %2;" : "=r"(r) : "f"(hi), "f"(lo));
    return r;
}
__device__ __forceinline__ void mma_tf32(float c[4],
    uint32_t a0, uint32_t a1, uint32_t a2, uint32_t a3,
    uint32_t b0, uint32_t b1)
{
    asm("mma.sync.aligned.m16n8k8.row.col.f32.tf32.tf32.f32 "
        "{%0,%1,%2,%3},{%4,%5,%6,%7},{%8,%9},{%0,%1,%2,%3};"
        : "+f"(c[0]), "+f"(c[1]), "+f"(c[2]), "+f"(c[3])
        : "r"(a0), "r"(a1), "r"(a2), "r"(a3), "r"(b0), "r"(b1));
}
__device__ __forceinline__ void mma_f16(float c[4],
    uint32_t a0, uint32_t a1, uint32_t a2, uint32_t a3,
    uint32_t b0, uint32_t b1)
{
    asm("mma.sync.aligned.m16n8k16.row.col.f32.f16.f16.f32 "
        "{%0,%1,%2,%3},{%4,%5,%6,%7},{%8,%9},{%0,%1,%2,%3};"
        : "+f"(c[0]), "+f"(c[1]), "+f"(c[2]), "+f"(c[3])
        : "r"(a0), "r"(a1), "r"(a2), "r"(a3), "r"(b0), "r"(b1));
}

// ---------------- weight transpose+convert: out[n][k] = (half)in[k][n] ----------------
__global__ void transpose_h_kernel(const float* __restrict__ in, __half* __restrict__ out,
                                   int K, int N, size_t in_ls, size_t out_ls)
{
    __shared__ __half s[32][33];
    const float* ip = in + blockIdx.z * in_ls;
    __half*      op = out + blockIdx.z * out_ls;
    int n0 = blockIdx.x*32, k0 = blockIdx.y*32;
    int tx = threadIdx.x, ty = threadIdx.y;   // 32 x 8
    #pragma unroll
    for (int i = 0; i < 4; i++)
        s[ty + 8*i][tx] = __float2half_rn(ip[(size_t)(k0 + ty + 8*i)*N + n0 + tx]);
    __syncthreads();
    #pragma unroll
    for (int i = 0; i < 4; i++)
        op[(size_t)(n0 + ty + 8*i)*K + k0 + tx] = s[tx][ty + 8*i];
}

// ---------------- embedding + sinusoidal positional encoding ----------------
__global__ void embed_kernel(const int* __restrict__ X,
                             const float* __restrict__ emb,
                             float* __restrict__ h)
{
    int row = blockIdx.x;
    int s = row % SEQ;
    int tok = X[row];
    const float scale = 32.0f;
    const float l2 = 13.28771238f;
    for (int d = threadIdx.x; d < DM; d += blockDim.x) {
        int j = d & ~1;
        float freq = exp2f(-((float)j / (float)DM) * l2);
        float ang  = (float)s * freq;
        float sn, cs;
        sincosf(ang, &sn, &cs);
        float p = (d & 1) ? cs : sn;
        h[row*DM + d] = emb[tok*DM + d] * scale + p;
    }
}

// ---------------- fp16 tensor-core GEMM ----------------
// A fp32 [M][K] (cvt to half in-kernel), B half [N][K] (pre-transposed), C fp32.
// Block tile (WM*32)x(WN*32)x32, warp tile 32x32, mma m16n8k16 f16 fp32-acc.
// SMEM rows = 16 u32 (half2 pairs), swizzle c ^= ((row>>1)&3)<<2 (conflict-free,
// enumerated). Double buffered. MX=1: M-fastest grid for B-band L2 reuse.
template<int WM, int WN, int MX>
__global__ void __launch_bounds__(WM*WN*32, (WM*WN == 4) ? 4 : 1)
hgemm_kernel(const float* __restrict__ A, PtrsN P,
             const float* __restrict__ bias, int M, int N, int K, int relu)
{
    constexpr int BM  = WM*32;
    constexpr int BN  = WN*32;
    constexpr int T   = WM*WN*32;
    constexpr int ITA = BM*8 / T;    // A: BM rows x 8 float4 chunks
    constexpr int ITB = BN*4 / T;    // B: BN rows x 4 uint4 chunks (8 halves)
    constexpr int SZA = BM*16;       // u32 words
    constexpr int SZB = BN*16;

    extern __shared__ __align__(16) uint32_t smem_u[];
    uint32_t* sA = smem_u;           // [2][SZA]
    uint32_t* sB = smem_u + 2*SZA;   // [2][SZB]

    const __half* __restrict__ Bp = P.B[blockIdx.z];
    float*        __restrict__ Cp = P.C[blockIdx.z];

    const int tid  = threadIdx.x;
    const int br   = (MX ? blockIdx.x : blockIdx.y) * BM;
    const int bc   = (MX ? blockIdx.y : blockIdx.x) * BN;
    const int wid  = tid >> 5;
    const int lane = tid & 31;
    const int wm   = wid / WN;
    const int wn   = wid % WN;
    const int rl   = lane >> 2;
    const int w    = lane & 3;

    float acc[2][4][4];
    #pragma unroll
    for (int im = 0; im < 2; im++)
        #pragma unroll
        for (int in = 0; in < 4; in++)
            #pragma unroll
            for (int t = 0; t < 4; t++) acc[im][in][t] = 0.f;

    float4 ra[ITA];
    uint4  rb[ITB];
    const int nkt = K >> 5;

    #pragma unroll
    for (int i = 0; i < ITA; i++) {
        int L = i*T + tid, m = L >> 3, c = L & 7;
        ra[i] = *(const float4*)&A[(size_t)(br+m)*K + c*4];
    }
    #pragma unroll
    for (int i = 0; i < ITB; i++) {
        int L = i*T + tid, n = L >> 2, c4 = L & 3;
        rb[i] = *(const uint4*)&Bp[(size_t)(bc+n)*K + c4*8];
    }
    #pragma unroll
    for (int i = 0; i < ITA; i++) {
        int L = i*T + tid, m = L >> 3, c = L & 7;
        uint2 u;
        u.x = f2h2(ra[i].x, ra[i].y);
        u.y = f2h2(ra[i].z, ra[i].w);
        *(uint2*)&sA[m*16 + ((c*2) ^ (((m>>1)&3)<<2))] = u;
    }
    #pragma unroll
    for (int i = 0; i < ITB; i++) {
        int L = i*T + tid, n = L >> 2, c4 = L & 3;
        *(uint4*)&sB[n*16 + ((c4*4) ^ (((n>>1)&3)<<2))] = rb[i];
    }
    __syncthreads();

    for (int kt = 0; kt < nkt; kt++) {
        const int st = kt & 1;
        if (kt + 1 < nkt) {
            int k0 = (kt + 1) << 5;
            #pragma unroll
            for (int i = 0; i < ITA; i++) {
                int L = i*T + tid, m = L >> 3, c = L & 7;
                ra[i] = *(const float4*)&A[(size_t)(br+m)*K + k0 + c*4];
            }
            #pragma unroll
            for (int i = 0; i < ITB; i++) {
                int L = i*T + tid, n = L >> 2, c4 = L & 3;
                rb[i] = *(const uint4*)&Bp[(size_t)(bc+n)*K + k0 + c4*8];
            }
        }

        const uint32_t* __restrict__ pA = sA + st*SZA;
        const uint32_t* __restrict__ pB = sB + st*SZB;
        #pragma unroll
        for (int kc = 0; kc < 2; kc++) {
            const int p0 = kc*8 + w;
            const int p1 = p0 + 4;
            uint32_t a[2][4], b[4][2];
            #pragma unroll
            for (int im = 0; im < 2; im++) {
                int r  = wm*32 + im*16 + rl;
                int sz = ((r>>1)&3)<<2;
                a[im][0] = pA[ r     *16 + (p0 ^ sz)];
                a[im][1] = pA[(r + 8)*16 + (p0 ^ sz)];
                a[im][2] = pA[ r     *16 + (p1 ^ sz)];
                a[im][3] = pA[(r + 8)*16 + (p1 ^ sz)];
            }
            #pragma unroll
            for (int in = 0; in < 4; in++) {
                int n  = wn*32 + in*8 + rl;
                int sz = ((n>>1)&3)<<2;
                b[in][0] = pB[n*16 + (p0 ^ sz)];
                b[in][1] = pB[n*16 + (p1 ^ sz)];
            }
            #pragma unroll
            for (int im = 0; im < 2; im++)
                #pragma unroll
                for (int in = 0; in < 4; in++)
                    mma_f16(acc[im][in], a[im][0], a[im][1], a[im][2], a[im][3],
                            b[in][0], b[in][1]);
        }

        if (kt + 1 < nkt) {
            const int sn = st ^ 1;
            #pragma unroll
            for (int i = 0; i < ITA; i++) {
                int L = i*T + tid, m = L >> 3, c = L & 7;
                uint2 u;
                u.x = f2h2(ra[i].x, ra[i].y);
                u.y = f2h2(ra[i].z, ra[i].w);
                *(uint2*)&sA[sn*SZA + m*16 + ((c*2) ^ (((m>>1)&3)<<2))] = u;
            }
            #pragma unroll
            for (int i = 0; i < ITB; i++) {
                int L = i*T + tid, n = L >> 2, c4 = L & 3;
                *(uint4*)&sB[sn*SZB + n*16 + ((c4*4) ^ (((n>>1)&3)<<2))] = rb[i];
            }
        }
        __syncthreads();
    }

    const int r0 = br + wm*32 + rl;
    const int c0 = bc + wn*32 + w*2;
    #pragma unroll
    for (int im = 0; im < 2; im++) {
        int r = r0 + im*16;
        #pragma unroll
        for (int in = 0; in < 4; in++) {
            int c = c0 + in*8;
            float2 v0 = make_float2(acc[im][in][0], acc[im][in][1]);
            float2 v1 = make_float2(acc[im][in][2], acc[im][in][3]);
            if (bias) {
                float b0 = bias[c], b1 = bias[c+1];
                v0.x += b0; v0.y += b1; v1.x += b0; v1.y += b1;
            }
            if (relu) {
                v0.x = fmaxf(v0.x, 0.f); v0.y = fmaxf(v0.y, 0.f);
                v1.x = fmaxf(v1.x, 0.f); v1.y = fmaxf(v1.y, 0.f);
            }
            *(float2*)&Cp[(size_t)r     * N + c] = v0;
            *(float2*)&Cp[(size_t)(r+8) * N + c] = v1;
        }
    }
}

#define HS_22 ((2*(64*16)  + 2*(64*16))  * 4)   // 16 KB
#define HS_44 ((2*(128*16) + 2*(128*16)) * 4)   // 32 KB

static void hgemm64(const float* A, const __half* B, const float* bias, float* C,
                    int M, int N, int K, int relu)
{
    PtrsN P; P.B[0]=B; P.C[0]=C;
    dim3 grid(N/64, M/64, 1);
    hgemm_kernel<2,2,0><<<grid, 128, HS_22>>>(A, P, bias, M, N, K, relu);
}
static void hgemm_big(const float* A, PtrsN P, const float* bias, int z,
                      int M, int N, int K, int relu)
{
    dim3 grid(M/128, N/128, z);
    hgemm_kernel<4,4,1><<<grid, 512, HS_44>>>(A, P, bias, M, N, K, relu);
}

// ---------------- fused flash attention (unchanged from round 5) ----------------
#define PS  68
#define PSC 260
#define FLASH_SMEM ((2*64*PS + 64*PSC) * 4)

__global__ void __launch_bounds__(128)
flash_attn_kernel(const float* __restrict__ Q, const float* __restrict__ Kv,
                  const float* __restrict__ Vv, float* __restrict__ O,
                  const int* __restrict__ valid, int mode)
{
    extern __shared__ uint32_t sm[];
    uint32_t* Qs  = sm;
    uint32_t* KVs = sm + 64*PS;
    float*    Sc  = (float*)(sm + 2*64*PS);

    const int bh = blockIdx.y, b = bh >> 4, h = bh & 15;
    const int i0 = blockIdx.x * 64;
    const int tid = threadIdx.x;
    const int wid = tid >> 5, lane = tid & 31;
    const int rl = lane >> 2, w = lane & 3;
    const int wq = wid * 16;

    for (int t = tid; t < 64*16; t += 128) {
        int r = t >> 4, c4 = t & 15;
        float4 f = *(const float4*)&Q[(size_t)(b*SEQ + i0 + r)*DM + h*DH + c4*4];
        uint4 u;
        u.x = f2tf32(f.x); u.y = f2tf32(f.y); u.z = f2tf32(f.z); u.w = f2tf32(f.w);
        *(uint4*)&Qs[r*PS + c4*4] = u;
    }

    const int vb = valid[b];
    const int iA = i0 + wq + rl;
    const int iB = iA + 8;
    const int vldA = (mode == 0) ? min(vb, iA + 1) : vb;
    const int vldB = (mode == 0) ? min(vb, iB + 1) : vb;

    for (int j0 = 0; j0 < SEQ; j0 += 64) {
        __syncthreads();
        for (int t = tid; t < 64*16; t += 128) {
            int r = t >> 4, c4 = t & 15;
            float4 f = *(const float4*)&Kv[(size_t)(b*SEQ + j0 + r)*DM + h*DH + c4*4];
            uint4 u;
            u.x = f2tf32(f.x); u.y = f2tf32(f.y); u.z = f2tf32(f.z); u.w = f2tf32(f.w);
            *(uint4*)&KVs[r*PS + c4*4] = u;
        }
        __syncthreads();

        float acc[8][4];
        #pragma unroll
        for (int nt = 0; nt < 8; nt++)
            #pragma unroll
            for (int t = 0; t < 4; t++) acc[nt][t] = 0.f;

        #pragma unroll
        for (int kk = 0; kk < 8; kk++) {
            int k0 = kk * 8;
            uint32_t a0 = Qs[(wq + rl    )*PS + k0 + w];
            uint32_t a1 = Qs[(wq + rl + 8)*PS + k0 + w];
            uint32_t a2 = Qs[(wq + rl    )*PS + k0 + w + 4];
            uint32_t a3 = Qs[(wq + rl + 8)*PS + k0 + w + 4];
            #pragma unroll
            for (int nt = 0; nt < 8; nt++) {
                uint32_t b0 = KVs[(nt*8 + rl)*PS + k0 + w];
                uint32_t b1 = KVs[(nt*8 + rl)*PS + k0 + w + 4];
                mma_tf32(acc[nt], a0, a1, a2, a3, b0, b1);
            }
        }

        #pragma unroll
        for (int nt = 0; nt < 8; nt++) {
            int j = j0 + nt*8 + w*2;
            float2 v0, v1;
            v0.x = (j     >= vldA) ? 1e-6f : acc[nt][0]*0.125f;
            v0.y = (j + 1 >= vldA) ? 1e-6f : acc[nt][1]*0.125f;
            v1.x = (j     >= vldB) ? 1e-6f : acc[nt][2]*0.125f;
            v1.y = (j + 1 >= vldB) ? 1e-6f : acc[nt][3]*0.125f;
            *(float2*)&Sc[(wq + rl    )*PSC + j] = v0;
            *(float2*)&Sc[(wq + rl + 8)*PSC + j] = v1;
        }
    }
    __syncthreads();

    for (int rr = 0; rr < 16; rr++) {
        float* p = Sc + (wq + rr)*PSC;
        float vals[8];
        float mx = -1e30f;
        #pragma unroll
        for (int t = 0; t < 8; t++) { vals[t] = p[lane + t*32]; mx = fmaxf(mx, vals[t]); }
        #pragma unroll
        for (int o = 16; o; o >>= 1) mx = fmaxf(mx, __shfl_xor_sync(0xffffffffu, mx, o));
        float sum = 0.f;
        #pragma unroll
        for (int t = 0; t < 8; t++) { vals[t] = expf(vals[t] - mx); sum += vals[t]; }
        #pragma unroll
        for (int o = 16; o; o >>= 1) sum += __shfl_xor_sync(0xffffffffu, sum, o);
        float inv = 1.0f / sum;
        #pragma unroll
        for (int t = 0; t < 8; t++) p[lane + t*32] = vals[t] * inv;
    }

    float oacc[8][4];
    #pragma unroll
    for (int nt = 0; nt < 8; nt++)
        #pragma unroll
        for (int t = 0; t < 4; t++) oacc[nt][t] = 0.f;

    for (int j0 = 0; j0 < SEQ; j0 += 64) {
        __syncthreads();
        for (int t = tid; t < 64*16; t += 128) {
            int j = t >> 4, c4 = t & 15;
            float4 f = *(const float4*)&Vv[(size_t)(b*SEQ + j0 + j)*DM + h*DH + c4*4];
            int d0 = c4*4;
            KVs[(d0  )*PS + (j ^ (((d0  )>>2)&15))] = f2tf32(f.x);
            KVs[(d0+1)*PS + (j ^ (((d0+1)>>2)&15))] = f2tf32(f.y);
            KVs[(d0+2)*PS + (j ^ (((d0+2)>>2)&15))] = f2tf32(f.z);
            KVs[(d0+3)*PS + (j ^ (((d0+3)>>2)&15))] = f2tf32(f.w);
        }
        __syncthreads();

        #pragma unroll
        for (int kk = 0; kk < 8; kk++) {
            int k0 = kk * 8;
            uint32_t a0 = f2tf32(Sc[(wq + rl    )*PSC + j0 + k0 + w]);
            uint32_t a1 = f2tf32(Sc[(wq + rl + 8)*PSC + j0 + k0 + w]);
            uint32_t a2 = f2tf32(Sc[(wq + rl    )*PSC + j0 + k0 + w + 4]);
            uint32_t a3 = f2tf32(Sc[(wq + rl + 8)*PSC + j0 + k0 + w + 4]);
            #pragma unroll
            for (int nt = 0; nt < 8; nt++) {
                int d  = nt*8 + rl;
                int fx = (d >> 2) & 15;
                uint32_t b0 = KVs[d*PS + ((k0 + w    ) ^ fx)];
                uint32_t b1 = KVs[d*PS + ((k0 + w + 4) ^ fx)];
                mma_tf32(oacc[nt], a0, a1, a2, a3, b0, b1);
            }
        }
    }

    #pragma unroll
    for (int nt = 0; nt < 8; nt++) {
        int d = nt*8 + w*2;
        *(float2*)&O[(size_t)(b*SEQ + iA)*DM + h*DH + d] = make_float2(oacc[nt][0], oacc[nt][1]);
        *(float2*)&O[(size_t)(b*SEQ + iB)*DM + h*DH + d] = make_float2(oacc[nt][2], oacc[nt][3]);
    }
}

// ---------------- out = LayerNorm(a + r) * g + be ----------------
__global__ void add_ln_kernel(const float* __restrict__ a, const float* __restrict__ r,
                              const float* __restrict__ g, const float* __restrict__ be,
                              float* __restrict__ out)
{
    int row = blockIdx.x;
    __shared__ float red[256];
    float x[4];
    #pragma unroll
    for (int t = 0; t < 4; t++) {
        int c = threadIdx.x + t*256;
        x[t] = a[row*DM + c] + r[row*DM + c];
    }
    float s = x[0] + x[1] + x[2] + x[3];
    red[threadIdx.x] = s; __syncthreads();
    for (int o = 128; o; o >>= 1) {
        if (threadIdx.x < o) red[threadIdx.x] += red[threadIdx.x + o];
        __syncthreads();
    }
    float mean = red[0] * (1.0f / DM);
    __syncthreads();
    float vs = 0.f;
    #pragma unroll
    for (int t = 0; t < 4; t++) { float d = x[t] - mean; vs += d*d; }
    red[threadIdx.x] = vs; __syncthreads();
    for (int o = 128; o; o >>= 1) {
        if (threadIdx.x < o) red[threadIdx.x] += red[threadIdx.x + o];
        __syncthreads();
    }
    float inv = rsqrtf(red[0] * (1.0f / DM) + 1e-5f);
    #pragma unroll
    for (int t = 0; t < 4; t++) {
        int c = threadIdx.x + t*256;
        out[row*DM + c] = (x[t] - mean) * inv * g[c] + be[c];
    }
}

// ---------------- host orchestration ----------------
extern "C" void kernel_launch(void* const* d_in, const int* in_sizes, int n_in,
                              void* d_out, int out_size)
{
    const int*   X         = (const int*)  d_in[0];
    const int*   dec_valid = (const int*)  d_in[1];
    const float* enc_out   = (const float*)d_in[2];
    const int*   enc_valid = (const int*)  d_in[3];
    const float* emb       = (const float*)d_in[4];
    const float* Wq1 = (const float*)d_in[5];
    const float* Wk1 = (const float*)d_in[6];
    const float* Wv1 = (const float*)d_in[7];
    const float* Wo1 = (const float*)d_in[8];
    const float* Wq2 = (const float*)d_in[9];
    const float* Wk2 = (const float*)d_in[10];
    const float* Wv2 = (const float*)d_in[11];
    const float* Wo2 = (const float*)d_in[12];
    const float* W1  = (const float*)d_in[13];
    const float* W2  = (const float*)d_in[14];
    const float* Wout= (const float*)d_in[15];
    const float* b1  = (const float*)d_in[16];
    const float* b2  = (const float*)d_in[17];
    const float* bout= (const float*)d_in[18];
    const float* ln1g= (const float*)d_in[19];
    const float* ln1b= (const float*)d_in[20];
    const float* ln2g= (const float*)d_in[21];
    const float* ln2b= (const float*)d_in[22];
    const float* ln3g= (const float*)d_in[23];
    const float* ln3b= (const float*)d_in[24];
    float* out = (float*)d_out;

    float *h, *q, *k, *v, *attn, *proj, *y, *y2, *ffn, *ffn2, *k2, *v2;
    cudaGetSymbolAddress((void**)&h,    g_h);
    cudaGetSymbolAddress((void**)&q,    g_q);
    cudaGetSymbolAddress((void**)&k,    g_k);
    cudaGetSymbolAddress((void**)&v,    g_v);
    cudaGetSymbolAddress((void**)&attn, g_attn);
    cudaGetSymbolAddress((void**)&proj, g_proj);
    cudaGetSymbolAddress((void**)&y,    g_y);
    cudaGetSymbolAddress((void**)&y2,   g_y2);
    cudaGetSymbolAddress((void**)&ffn,  g_ffn);
    cudaGetSymbolAddress((void**)&ffn2, g_ffn2);
    cudaGetSymbolAddress((void**)&k2,   g_k2);
    cudaGetSymbolAddress((void**)&v2,   g_v2);

    __half *wq1h, *wk1h, *wv1h, *wo1h, *wq2h, *wk2h, *wv2h, *wo2h, *w1h, *w2h, *wouth;
    cudaGetSymbolAddress((void**)&wq1h, g_wq1h);
    cudaGetSymbolAddress((void**)&wk1h, g_wk1h);
    cudaGetSymbolAddress((void**)&wv1h, g_wv1h);
    cudaGetSymbolAddress((void**)&wo1h, g_wo1h);
    cudaGetSymbolAddress((void**)&wq2h, g_wq2h);
    cudaGetSymbolAddress((void**)&wk2h, g_wk2h);
    cudaGetSymbolAddress((void**)&wv2h, g_wv2h);
    cudaGetSymbolAddress((void**)&wo2h, g_wo2h);
    cudaGetSymbolAddress((void**)&w1h,  g_w1h);
    cudaGetSymbolAddress((void**)&w2h,  g_w2h);
    cudaGetSymbolAddress((void**)&wouth,g_wouth);

    static int attr_set = 0;
    if (!attr_set) {
        cudaFuncSetAttribute(flash_attn_kernel,
                             cudaFuncAttributeMaxDynamicSharedMemorySize, FLASH_SMEM);
        cudaFuncSetAttribute(hgemm_kernel<4,4,1>,
                             cudaFuncAttributeMaxDynamicSharedMemorySize, HS_44);
        attr_set = 1;
    }

    // ---- weight transpose+convert (per call; deterministic) ----
    {
        dim3 tb(32, 8);
        dim3 gsq(DM/32, DM/32, NL);
        size_t sq = (size_t)DM*DM;
        transpose_h_kernel<<<gsq, tb>>>(Wq1, wq1h, DM, DM, sq, sq);
        transpose_h_kernel<<<gsq, tb>>>(Wk1, wk1h, DM, DM, sq, sq);
        transpose_h_kernel<<<gsq, tb>>>(Wv1, wv1h, DM, DM, sq, sq);
        transpose_h_kernel<<<gsq, tb>>>(Wo1, wo1h, DM, DM, sq, sq);
        transpose_h_kernel<<<gsq, tb>>>(Wq2, wq2h, DM, DM, sq, sq);
        transpose_h_kernel<<<gsq, tb>>>(Wk2, wk2h, DM, DM, sq, sq);
        transpose_h_kernel<<<gsq, tb>>>(Wv2, wv2h, DM, DM, sq, sq);
        transpose_h_kernel<<<gsq, tb>>>(Wo2, wo2h, DM, DM, sq, sq);
        size_t rct = (size_t)DM*HID;
        transpose_h_kernel<<<dim3(HID/32, DM/32, NL), tb>>>(W1, w1h, DM, HID, rct, rct);
        transpose_h_kernel<<<dim3(DM/32, HID/32, NL), tb>>>(W2, w2h, HID, DM, rct, rct);
        transpose_h_kernel<<<dim3(VOCAB/32, DM/32, 1), tb>>>(Wout, wouth, DM, VOCAB,
                                                             0, 0);
    }

    embed_kernel<<<ROWS, 256>>>(X, emb, h);

    // hoisted cross-attention K/V projections for ALL layers
    {
        PtrsN P;
        for (int l = 0; l < NL; l++) {
            P.B[l*2  ] = wk2h + (size_t)l*DM*DM;
            P.B[l*2+1] = wv2h + (size_t)l*DM*DM;
            P.C[l*2  ] = k2 + (size_t)l*ROWS*DM;
            P.C[l*2+1] = v2 + (size_t)l*ROWS*DM;
        }
        hgemm_big(enc_out, P, nullptr, 2*NL, ROWS, DM, DM, 0);
    }

    dim3 fgrid(SEQ/64, BZ*NH);

    for (int l = 0; l < NL; l++) {
        const size_t o2 = (size_t)l*DM*DM;
        // ---- self attention ----
        {
            PtrsN P;
            P.B[0]=wq1h+o2; P.B[1]=wk1h+o2; P.B[2]=wv1h+o2;
            P.C[0]=q;       P.C[1]=k;       P.C[2]=v;
            hgemm_big(h, P, nullptr, 3, ROWS, DM, DM, 0);
        }
        flash_attn_kernel<<<fgrid, 128, FLASH_SMEM>>>(q, k, v, attn, dec_valid, 0);
        hgemm64(attn, wo1h+o2, nullptr, proj, ROWS, DM, DM, 0);
        add_ln_kernel<<<ROWS, 256>>>(h, proj, ln1g + l*DM, ln1b + l*DM, y);
        // ---- cross attention (K/V precomputed) ----
        hgemm64(y, wq2h+o2, nullptr, q, ROWS, DM, DM, 0);
        flash_attn_kernel<<<fgrid, 128, FLASH_SMEM>>>(
            q, k2 + (size_t)l*ROWS*DM, v2 + (size_t)l*ROWS*DM, attn, enc_valid, 1);
        hgemm64(attn, wo2h+o2, nullptr, proj, ROWS, DM, DM, 0);
        add_ln_kernel<<<ROWS, 256>>>(y, proj, ln2g + l*DM, ln2b + l*DM, y2);
        // ---- FFN ----
        {
            PtrsN P;
            P.B[0] = w1h + (size_t)l*HID*DM;
            P.C[0] = ffn;
            hgemm_big(y2, P, b1 + l*HID, 1, ROWS, HID, DM, 1);
        }
        hgemm64(ffn, w2h + (size_t)l*DM*HID, b2 + l*DM, ffn2, ROWS, DM, HID, 0);
        add_ln_kernel<<<ROWS, 256>>>(y2, ffn2, ln3g + l*DM, ln3b + l*DM, h);
    }
    // ---- final vocab projection ----
    {
        PtrsN P;
        P.B[0] = wouth;
        P.C[0] = out;
        hgemm_big(h, P, bout, 1, ROWS, VOCAB, DM, 0);
    }
}